// round 14
// baseline (speedup 1.0000x reference)
#include <cuda_runtime.h>
#include <math.h>
#include <stdint.h>

#define NN 50000
#define NE 600000
#define NG 128
#define CDIM 128
#define M3 384
#define CAT 1152
#define EPSB 1e-5f
#define SCAN_T 1024
#define AST 36                       // smem row stride (words)
#define GSMEM (4 * 128 * AST * 4)    // 2 stages x (A+W) x 128x36 words

// ---------------- static scratch (no allocations allowed) ----------------
__device__ float d_neigh[(size_t)NN * CDIM];
__device__ float d_Xr[(size_t)NN * CDIM];
__device__ float d_xr[(size_t)NN * CDIM];
__device__ float d_H1[(size_t)NN * CDIM];
__device__ float d_H2[(size_t)NN * CDIM];
__device__ float d_Hm[(size_t)NN * M3];
__device__ float d_wrelt[CDIM * CDIM];
__device__ float d_wroott[CDIM * CDIM];
__device__ float d_linwt[M3 * M3];
__device__ float d_linbt[M3];
__device__ float d_stX[2 * CDIM];
__device__ float d_scX[CDIM];
__device__ float d_shX[CDIM];
__device__ float d_scH[M3];
__device__ float d_shH[M3];
__device__ float d_gsum[NG * M3];
__device__ float d_gsq[NG * M3];
__device__ float d_gmax[NG * M3];
__device__ float d_gmin[NG * M3];
__device__ int   d_gcnt[NG];
__device__ float d_Hcat[NG * CAT];
__device__ float d_Hbn[NG * CAT];
__device__ float d_h1[NG * 768];
__device__ float d_h2[NG * 384];
// CSR scratch
__device__ int d_degc[NN], d_degr[NN];
__device__ int d_offc[NN + 1], d_offr[NN + 1];
__device__ int d_curc[NN], d_curr[NN];
__device__ int d_srcc[NE];
__device__ int d_srcr[NE];

// ---------------- tf32 helpers ----------------
__device__ __forceinline__ unsigned f2tf32(float v) {
    unsigned r;
    asm("cvt.rna.tf32.f32 %0, %1;" : "=r"(r) : "f"(v));
    return r;
}
__device__ __forceinline__ float rnd_tf32(float v) { return __uint_as_float(f2tf32(v)); }
__device__ __forceinline__ void mma_tf32(float* c, const unsigned* a, const unsigned* b) {
    asm volatile(
        "mma.sync.aligned.m16n8k8.row.col.f32.tf32.tf32.f32 "
        "{%0,%1,%2,%3}, {%4,%5,%6,%7}, {%8,%9}, {%0,%1,%2,%3};"
        : "+f"(c[0]), "+f"(c[1]), "+f"(c[2]), "+f"(c[3])
        : "r"(a[0]), "r"(a[1]), "r"(a[2]), "r"(a[3]), "r"(b[0]), "r"(b[1]));
}
// ---------------- cp.async helpers ----------------
__device__ __forceinline__ void cpa16(uint32_t saddr, const void* g, int bytes) {
    asm volatile("cp.async.cg.shared.global [%0], [%1], 16, %2;"
                 :: "r"(saddr), "l"(g), "r"(bytes));
}
__device__ __forceinline__ void cpa_commit() { asm volatile("cp.async.commit_group;"); }
__device__ __forceinline__ void cpa_wait1() { asm volatile("cp.async.wait_group 1;"); }
__device__ __forceinline__ void cpa_wait0() { asm volatile("cp.async.wait_group 0;"); }

// ---------------- init: zero degrees + stats accumulators ----------------
__global__ void init_k() {
    int i = blockIdx.x * blockDim.x + threadIdx.x;
    if (i < NN) { d_degc[i] = 0; d_degr[i] = 0; }
    if (i < 2 * CDIM) d_stX[i] = 0.f;
}

// ---------------- degree histogram ----------------
__global__ void hist_k(const int* __restrict__ row, const int* __restrict__ col) {
    int e = blockIdx.x * blockDim.x + threadIdx.x;
    if (e >= NE) return;
    atomicAdd(&d_degc[__ldg(col + e)], 1);
    atomicAdd(&d_degr[__ldg(row + e)], 1);
}

// ---------------- exclusive scan (single block per array) ----------------
__global__ void scan_k() {
    __shared__ int sm[SCAN_T];
    const int* deg = (blockIdx.x == 0) ? d_degc : d_degr;
    int* off = (blockIdx.x == 0) ? d_offc : d_offr;
    int* cur = (blockIdx.x == 0) ? d_curc : d_curr;
    int t = threadIdx.x;
    const int CH = (NN + SCAN_T - 1) / SCAN_T;
    int b = t * CH, e = min(b + CH, NN);
    int s = 0;
    for (int i = b; i < e; i++) s += deg[i];
    sm[t] = s;
    __syncthreads();
    for (int d = 1; d < SCAN_T; d <<= 1) {
        int u = (t >= d) ? sm[t - d] : 0;
        __syncthreads();
        sm[t] += u;
        __syncthreads();
    }
    int p = (t == 0) ? 0 : sm[t - 1];
    for (int i = b; i < e; i++) {
        off[i] = p;
        cur[i] = p;
        p += deg[i];
    }
    if (t == SCAN_T - 1) off[NN] = sm[SCAN_T - 1];
}

// ---------------- fill CSR edge lists ----------------
__global__ void fill_k(const int* __restrict__ row, const int* __restrict__ col) {
    int e = blockIdx.x * blockDim.x + threadIdx.x;
    if (e >= NE) return;
    int r = __ldg(row + e), c = __ldg(col + e);
    int pc = atomicAdd(&d_curc[c], 1);
    d_srcc[pc] = r;
    int pr = atomicAdd(&d_curr[r], 1);
    d_srcr[pr] = c;
}

// ---------------- round-copy (tf32 quantize); also handles both weights in one launch ----------------
__global__ void round_copy_k(const float* __restrict__ src, float* __restrict__ dst, int n) {
    int i = blockIdx.x * blockDim.x + threadIdx.x;
    if (i < n) dst[i] = rnd_tf32(__ldg(src + i));
}
__global__ void round_weights_k(const float* __restrict__ wrel, const float* __restrict__ wroot) {
    int i = blockIdx.x * blockDim.x + threadIdx.x;  // 0..16383
    d_wrelt[i] = rnd_tf32(__ldg(wrel + i));
    d_wroott[i] = rnd_tf32(__ldg(wroot + i));
}

// ---------------- CSR gather-accumulate (MLP-4 unrolled); stores tf32-rounded ----------------
__global__ void spmm_csr_k(const float* __restrict__ src, float* __restrict__ dst,
                           const int* __restrict__ off, const int* __restrict__ idx,
                           const float* __restrict__ sc, const float* __restrict__ sh) {
    int node = blockIdx.x * 8 + (threadIdx.x >> 5);
    if (node >= NN) return;
    int q = threadIdx.x & 31;
    int beg = __ldg(off + node), end = __ldg(off + node + 1);
    float4 acc = make_float4(0.f, 0.f, 0.f, 0.f);
    int e = beg;
    for (; e + 3 < end; e += 4) {
        int s0 = __ldg(idx + e), s1 = __ldg(idx + e + 1);
        int s2 = __ldg(idx + e + 2), s3 = __ldg(idx + e + 3);
        float4 v0 = __ldg((const float4*)src + (size_t)s0 * 32 + q);
        float4 v1 = __ldg((const float4*)src + (size_t)s1 * 32 + q);
        float4 v2 = __ldg((const float4*)src + (size_t)s2 * 32 + q);
        float4 v3 = __ldg((const float4*)src + (size_t)s3 * 32 + q);
        acc.x += (v0.x + v1.x) + (v2.x + v3.x);
        acc.y += (v0.y + v1.y) + (v2.y + v3.y);
        acc.z += (v0.z + v1.z) + (v2.z + v3.z);
        acc.w += (v0.w + v1.w) + (v2.w + v3.w);
    }
    for (; e < end; ++e) {
        int s0 = __ldg(idx + e);
        float4 v0 = __ldg((const float4*)src + (size_t)s0 * 32 + q);
        acc.x += v0.x; acc.y += v0.y; acc.z += v0.z; acc.w += v0.w;
    }
    if (sc) {
        float d = (float)(end - beg);
        float4 s4 = __ldg((const float4*)sc + q);
        float4 h4 = __ldg((const float4*)sh + q);
        acc.x = fmaf(acc.x, s4.x, h4.x * d);
        acc.y = fmaf(acc.y, s4.y, h4.y * d);
        acc.z = fmaf(acc.z, s4.z, h4.z * d);
        acc.w = fmaf(acc.w, s4.w, h4.w * d);
    }
    acc.x = rnd_tf32(acc.x); acc.y = rnd_tf32(acc.y);
    acc.z = rnd_tf32(acc.z); acc.w = rnd_tf32(acc.w);
    ((float4*)dst)[(size_t)node * 32 + q] = acc;
}

// ---------------- stage issue helper for async GEMM ----------------
__device__ __forceinline__ void gemm_issue_stage(
    const float* const* Ap, const float* const* Wp, int st, int ldw,
    int r0, int rrb, int kq, uint32_t sbase, int BUF) {
    const float* A = Ap[st >> 2];
    const float* W = Wp[st >> 2];
    int kb = (st & 3) * 32;
    uint32_t abase = sbase + (uint32_t)((st & 1) * BUF) * 4;
    uint32_t wbase = abase + 128 * AST * 4;
#pragma unroll
    for (int it = 0; it < 4; ++it) {
        int rr = rrb + it * 32;
        int r = r0 + rr;
        int ok = (r < NN);
        const float* ga = A + (size_t)(ok ? r : 0) * CDIM + kb + kq;
        cpa16(abase + (uint32_t)(rr * AST + kq) * 4, ga, ok ? 16 : 0);
        cpa16(wbase + (uint32_t)(rr * AST + kq) * 4, W + (size_t)rr * ldw + kb + kq, 16);
    }
    cpa_commit();
}

// ================= tf32 GEMM core, cp.async double-buffered =================
__device__ __forceinline__ void gemm_core_async(
    const float* const* Ap, const float* const* Wp, int nIn, int ldw,
    const float* __restrict__ bias, float* __restrict__ Cp, int ldc,
    int r0, int cbase, int round_primary, unsigned* smemu) {
    const int tx = threadIdx.x;
    const int lane = tx & 31;
    const int warp = tx >> 5;
    const int wr = (warp & 3) * 32;
    const int wc = (warp >> 2) * 64;
    const int g = lane >> 2;
    const int t4 = lane & 3;
    const int rrb = tx >> 3;        // 0..31
    const int kq = (tx & 7) * 4;    // 0..28
    const uint32_t sbase = (uint32_t)__cvta_generic_to_shared(smemu);
    const int BUF = 2 * 128 * AST;  // words per stage (A+W)

    float acc[2][8][4];
#pragma unroll
    for (int mi = 0; mi < 2; mi++)
#pragma unroll
        for (int ni = 0; ni < 8; ni++)
#pragma unroll
            for (int j = 0; j < 4; j++) acc[mi][ni][j] = 0.f;

    const int nSteps = nIn * 4;

    gemm_issue_stage(Ap, Wp, 0, ldw, r0, rrb, kq, sbase, BUF);
    for (int st = 0; st < nSteps; ++st) {
        if (st + 1 < nSteps) {
            gemm_issue_stage(Ap, Wp, st + 1, ldw, r0, rrb, kq, sbase, BUF);
            cpa_wait1();
        } else {
            cpa_wait0();
        }
        __syncthreads();
        const unsigned* Ab = smemu + (st & 1) * BUF;
        const unsigned* Wb = Ab + 128 * AST;
#pragma unroll
        for (int kk = 0; kk < 32; kk += 8) {
            unsigned a[2][4], b[8][2];
#pragma unroll
            for (int mi = 0; mi < 2; mi++) {
                int r = wr + mi * 16;
                a[mi][0] = Ab[(r + g) * AST + kk + t4];
                a[mi][1] = Ab[(r + g + 8) * AST + kk + t4];
                a[mi][2] = Ab[(r + g) * AST + kk + t4 + 4];
                a[mi][3] = Ab[(r + g + 8) * AST + kk + t4 + 4];
            }
#pragma unroll
            for (int ni = 0; ni < 8; ni++) {
                int n = wc + ni * 8 + g;
                b[ni][0] = Wb[n * AST + kk + t4];
                b[ni][1] = Wb[n * AST + kk + t4 + 4];
            }
#pragma unroll
            for (int mi = 0; mi < 2; mi++)
#pragma unroll
                for (int ni = 0; ni < 8; ni++)
                    mma_tf32(acc[mi][ni], a[mi], b[ni]);
        }
        __syncthreads();
    }

    // epilogue: bias, optional tf32 rounding, write
#pragma unroll
    for (int mi = 0; mi < 2; mi++) {
        int r1 = r0 + wr + mi * 16 + g;
        int r2 = r1 + 8;
#pragma unroll
        for (int ni = 0; ni < 8; ni++) {
            int cc = wc + ni * 8 + 2 * t4;
            float b0 = bias[cc], b1 = bias[cc + 1];
            if (r1 < NN) {
                float v0 = acc[mi][ni][0] + b0, v1 = acc[mi][ni][1] + b1;
                if (round_primary) { v0 = rnd_tf32(v0); v1 = rnd_tf32(v1); }
                Cp[(size_t)r1 * ldc + cbase + cc] = v0;
                Cp[(size_t)r1 * ldc + cbase + cc + 1] = v1;
            }
            if (r2 < NN) {
                float v2 = acc[mi][ni][2] + b0, v3 = acc[mi][ni][3] + b1;
                if (round_primary) { v2 = rnd_tf32(v2); v3 = rnd_tf32(v3); }
                Cp[(size_t)r2 * ldc + cbase + cc] = v2;
                Cp[(size_t)r2 * ldc + cbase + cc + 1] = v3;
            }
        }
    }
}

// Xr = tf32( neigh @ w_rel^T + xr @ w_root^T + b_rel )
__global__ void __launch_bounds__(256, 2) gemm_x_k(const float* __restrict__ bias) {
    extern __shared__ unsigned smemu[];
    const float* Ap[3] = {d_neigh, d_xr, nullptr};
    const float* Wp[3] = {d_wrelt, d_wroott, nullptr};
    gemm_core_async(Ap, Wp, 2, 128, bias, d_Xr, 128, blockIdx.x * 128, 0, 1, smemu);
}

// Hm strips with BN(X) folded into transformed weights/bias
__global__ void __launch_bounds__(256, 2) gemm_hm_k() {
    extern __shared__ unsigned smemu[];
    int j = blockIdx.y;
    const float* Ap[3] = {d_Xr, d_H1, d_H2};
    const float* Wp[3];
    for (int i = 0; i < 3; i++)
        Wp[i] = d_linwt + (size_t)(j * 128) * M3 + i * 128;
    gemm_core_async(Ap, Wp, j + 1, M3, d_linbt + j * 128, d_Hm, M3,
                    blockIdx.x * 128, j * 128, 0, smemu);
}

// ---------------- per-column sum/sumsq over NN rows (X only; 2-way ILP) ----------------
__global__ void stats2_k(const float* __restrict__ A, int ncol, float* __restrict__ st,
                         int rows_per_blk) {
    __shared__ float sm[384 * 8];
    int n4 = ncol >> 2;
    int c4 = threadIdx.x % n4;
    int rl = threadIdx.x / n4;
    int rstep = blockDim.x / n4;
    int r0 = blockIdx.x * rows_per_blk;
    int rend = min(r0 + rows_per_blk, NN);
    float4 s = make_float4(0, 0, 0, 0), q = make_float4(0, 0, 0, 0);
    float4 s2 = make_float4(0, 0, 0, 0), q2 = make_float4(0, 0, 0, 0);
    int r = r0 + rl;
    for (; r + rstep < rend; r += 2 * rstep) {
        float4 v = __ldg((const float4*)(A + (size_t)r * ncol) + c4);
        float4 w = __ldg((const float4*)(A + (size_t)(r + rstep) * ncol) + c4);
        s.x += v.x; s.y += v.y; s.z += v.z; s.w += v.w;
        q.x += v.x * v.x; q.y += v.y * v.y; q.z += v.z * v.z; q.w += v.w * v.w;
        s2.x += w.x; s2.y += w.y; s2.z += w.z; s2.w += w.w;
        q2.x += w.x * w.x; q2.y += w.y * w.y; q2.z += w.z * w.z; q2.w += w.w * w.w;
    }
    if (r < rend) {
        float4 v = __ldg((const float4*)(A + (size_t)r * ncol) + c4);
        s.x += v.x; s.y += v.y; s.z += v.z; s.w += v.w;
        q.x += v.x * v.x; q.y += v.y * v.y; q.z += v.z * v.z; q.w += v.w * v.w;
    }
    s.x += s2.x; s.y += s2.y; s.z += s2.z; s.w += s2.w;
    q.x += q2.x; q.y += q2.y; q.z += q2.z; q.w += q2.w;
    float* my = sm + threadIdx.x * 8;
    my[0] = s.x; my[1] = s.y; my[2] = s.z; my[3] = s.w;
    my[4] = q.x; my[5] = q.y; my[6] = q.z; my[7] = q.w;
    __syncthreads();
    if (threadIdx.x < (unsigned)n4) {
        float acc[8];
#pragma unroll
        for (int k = 0; k < 8; k++) acc[k] = 0.f;
        for (int j = 0; j < rstep; j++) {
            float* p = sm + (c4 + j * n4) * 8;
#pragma unroll
            for (int k = 0; k < 8; k++) acc[k] += p[k];
        }
#pragma unroll
        for (int k = 0; k < 4; k++) {
            atomicAdd(st + c4 * 4 + k, acc[k]);
            atomicAdd(st + ncol + c4 * 4 + k, acc[4 + k]);
        }
    }
}

// ---------------- finalize BN(X): stats -> per-channel scale/shift ----------------
__global__ void finalize_bnX_k(const float* __restrict__ gw, const float* __restrict__ gb) {
    int c = threadIdx.x;  // 128
    float mean = d_stX[c] * (1.f / NN);
    float var = d_stX[CDIM + c] * (1.f / NN) - mean * mean;
    float sc = gw[c] * rsqrtf(var + EPSB);
    d_scX[c] = sc;
    d_shX[c] = gb[c] - mean * sc;
}

// ---------------- fold BN(X) into lin weights/bias; tf32-round all of lin_w ----------------
__global__ void lin_transform_k(const float* __restrict__ lin_w, const float* __restrict__ lin_b) {
    __shared__ float red[128];
    int o = blockIdx.x;   // 0..383
    int t = threadIdx.x;  // 0..127
    const float* wrow = lin_w + (size_t)o * M3;
    float w0 = wrow[t];
    d_linwt[(size_t)o * M3 + t] = rnd_tf32(w0 * d_scX[t]);
    d_linwt[(size_t)o * M3 + 128 + t] = rnd_tf32(wrow[128 + t]);
    d_linwt[(size_t)o * M3 + 256 + t] = rnd_tf32(wrow[256 + t]);
    red[t] = d_shX[t] * w0;
    __syncthreads();
    for (int s2 = 64; s2 > 0; s2 >>= 1) {
        if (t < s2) red[t] += red[t + s2];
        __syncthreads();
    }
    if (t == 0) d_linbt[o] = lin_b[o] + red[0];
}

// ---------------- per-graph raw pooling over Hm (2-way ILP) ----------------
__global__ void pool_raw_k(const int* __restrict__ batch) {
    __shared__ float sm[384 * 16];
    int gph = blockIdx.x;
    int tx = threadIdx.x;
    int c4 = tx % 96;
    int rl = tx / 96;
    int lo = 0, hi = NN;
    while (lo < hi) { int m = (lo + hi) >> 1; if (batch[m] < gph) lo = m + 1; else hi = m; }
    int start = lo;
    lo = start; hi = NN;
    while (lo < hi) { int m = (lo + hi) >> 1; if (batch[m] < gph + 1) lo = m + 1; else hi = m; }
    int end = lo;

    float4 s = make_float4(0, 0, 0, 0), q = make_float4(0, 0, 0, 0);
    float4 mx = make_float4(-INFINITY, -INFINITY, -INFINITY, -INFINITY);
    float4 mn = make_float4(INFINITY, INFINITY, INFINITY, INFINITY);
    float4 s2 = make_float4(0, 0, 0, 0), q2 = make_float4(0, 0, 0, 0);
    float4 mx2 = make_float4(-INFINITY, -INFINITY, -INFINITY, -INFINITY);
    float4 mn2 = make_float4(INFINITY, INFINITY, INFINITY, INFINITY);
    int r = start + rl;
    for (; r + 4 < end; r += 8) {
        float4 v = __ldg((const float4*)(d_Hm + (size_t)r * M3) + c4);
        float4 w = __ldg((const float4*)(d_Hm + (size_t)(r + 4) * M3) + c4);
        s.x += v.x; s.y += v.y; s.z += v.z; s.w += v.w;
        q.x += v.x * v.x; q.y += v.y * v.y; q.z += v.z * v.z; q.w += v.w * v.w;
        mx.x = fmaxf(mx.x, v.x); mx.y = fmaxf(mx.y, v.y);
        mx.z = fmaxf(mx.z, v.z); mx.w = fmaxf(mx.w, v.w);
        mn.x = fminf(mn.x, v.x); mn.y = fminf(mn.y, v.y);
        mn.z = fminf(mn.z, v.z); mn.w = fminf(mn.w, v.w);
        s2.x += w.x; s2.y += w.y; s2.z += w.z; s2.w += w.w;
        q2.x += w.x * w.x; q2.y += w.y * w.y; q2.z += w.z * w.z; q2.w += w.w * w.w;
        mx2.x = fmaxf(mx2.x, w.x); mx2.y = fmaxf(mx2.y, w.y);
        mx2.z = fmaxf(mx2.z, w.z); mx2.w = fmaxf(mx2.w, w.w);
        mn2.x = fminf(mn2.x, w.x); mn2.y = fminf(mn2.y, w.y);
        mn2.z = fminf(mn2.z, w.z); mn2.w = fminf(mn2.w, w.w);
    }
    for (; r < end; r += 4) {
        float4 v = __ldg((const float4*)(d_Hm + (size_t)r * M3) + c4);
        s.x += v.x; s.y += v.y; s.z += v.z; s.w += v.w;
        q.x += v.x * v.x; q.y += v.y * v.y; q.z += v.z * v.z; q.w += v.w * v.w;
        mx.x = fmaxf(mx.x, v.x); mx.y = fmaxf(mx.y, v.y);
        mx.z = fmaxf(mx.z, v.z); mx.w = fmaxf(mx.w, v.w);
        mn.x = fminf(mn.x, v.x); mn.y = fminf(mn.y, v.y);
        mn.z = fminf(mn.z, v.z); mn.w = fminf(mn.w, v.w);
    }
    s.x += s2.x; s.y += s2.y; s.z += s2.z; s.w += s2.w;
    q.x += q2.x; q.y += q2.y; q.z += q2.z; q.w += q2.w;
    mx.x = fmaxf(mx.x, mx2.x); mx.y = fmaxf(mx.y, mx2.y);
    mx.z = fmaxf(mx.z, mx2.z); mx.w = fmaxf(mx.w, mx2.w);
    mn.x = fminf(mn.x, mn2.x); mn.y = fminf(mn.y, mn2.y);
    mn.z = fminf(mn.z, mn2.z); mn.w = fminf(mn.w, mn2.w);

    float* my = sm + tx * 16;
    my[0] = s.x; my[1] = s.y; my[2] = s.z; my[3] = s.w;
    my[4] = q.x; my[5] = q.y; my[6] = q.z; my[7] = q.w;
    my[8] = mx.x; my[9] = mx.y; my[10] = mx.z; my[11] = mx.w;
    my[12] = mn.x; my[13] = mn.y; my[14] = mn.z; my[15] = mn.w;
    __syncthreads();
    if (rl == 0) {  // tx < 96
        float a[16];
#pragma unroll
        for (int k = 0; k < 16; k++) a[k] = my[k];
        for (int j = 1; j < 4; j++) {
            float* p = sm + (tx + j * 96) * 16;
#pragma unroll
            for (int k = 0; k < 4; k++) {
                a[k] += p[k];
                a[4 + k] += p[4 + k];
                a[8 + k] = fmaxf(a[8 + k], p[8 + k]);
                a[12 + k] = fminf(a[12 + k], p[12 + k]);
            }
        }
#pragma unroll
        for (int k = 0; k < 4; k++) {
            int col = c4 * 4 + k;
            d_gsum[gph * M3 + col] = a[k];
            d_gsq[gph * M3 + col] = a[4 + k];
            d_gmax[gph * M3 + col] = a[8 + k];
            d_gmin[gph * M3 + col] = a[12 + k];
        }
    }
    if (tx == 0) d_gcnt[gph] = end - start;
}

// ---------------- bnh BN scale/shift from per-graph sums ----------------
__global__ void stats_pool_k(const float* __restrict__ gw, const float* __restrict__ gb) {
    int c = blockIdx.x * 128 + threadIdx.x;  // 0..383
    float ts = 0.f, tq = 0.f;
    for (int g2 = 0; g2 < NG; g2++) {
        ts += d_gsum[g2 * M3 + c];
        tq += d_gsq[g2 * M3 + c];
    }
    float mean = ts * (1.f / NN);
    float var = tq * (1.f / NN) - mean * mean;
    float sc = gw[c] * rsqrtf(var + EPSB);
    d_scH[c] = sc;
    d_shH[c] = gb[c] - mean * sc;
}

// ---------------- emit Hcat (parallel over graphs) ----------------
__global__ void emit_hcat_k() {
    int g2 = blockIdx.x;      // graph
    int c = threadIdx.x;      // 0..383
    float sc = d_scH[c], sh = d_shH[c];
    int cnt = d_gcnt[g2];
    float add = sc * d_gsum[g2 * M3 + c] + sh * (float)cnt;
    float avg = (cnt > 0) ? add / (float)cnt : 0.f;
    float mxv = 0.f;
    if (cnt > 0)
        mxv = (sc >= 0.f) ? fmaf(sc, d_gmax[g2 * M3 + c], sh)
                          : fmaf(sc, d_gmin[g2 * M3 + c], sh);
    d_Hcat[(size_t)g2 * CAT + c] = avg;
    d_Hcat[(size_t)g2 * CAT + 384 + c] = add;
    d_Hcat[(size_t)g2 * CAT + 768 + c] = mxv;
}

// ---------------- BN over graphs ----------------
__global__ void bn_graphs_k(const float* __restrict__ gw, const float* __restrict__ gb) {
    int c = blockIdx.x * blockDim.x + threadIdx.x;
    if (c >= CAT) return;
    float s = 0.f, ss = 0.f;
    for (int r = 0; r < NG; r++) { float v = d_Hcat[r * CAT + c]; s += v; ss += v * v; }
    float mean = s * (1.f / NG);
    float var = ss * (1.f / NG) - mean * mean;
    float sc = gw[c] * rsqrtf(var + EPSB);
    float sh = gb[c] - mean * sc;
    for (int r = 0; r < NG; r++) d_Hbn[r * CAT + c] = fmaf(d_Hcat[r * CAT + c], sc, sh);
}

// ---------------- small dense layer ----------------
__global__ void mlp_k(const float* __restrict__ A, int Kd,
                      const float* __restrict__ W, const float* __restrict__ bias,
                      float* __restrict__ out, int Od, int do_relu) {
    extern __shared__ float sA[];
    int g0 = blockIdx.y * 8;
    for (int idx = threadIdx.x; idx < 8 * Kd; idx += blockDim.x)
        sA[idx] = A[(size_t)(g0 + idx / Kd) * Kd + (idx % Kd)];
    __syncthreads();
    int o = blockIdx.x * blockDim.x + threadIdx.x;
    float bb = bias[o];
    float acc[8];
#pragma unroll
    for (int j = 0; j < 8; j++) acc[j] = bb;
    const float* wr = W + (size_t)o * Kd;
    for (int k = 0; k < Kd; k++) {
        float w = wr[k];
#pragma unroll
        for (int j = 0; j < 8; j++) acc[j] = fmaf(w, sA[j * Kd + k], acc[j]);
    }
#pragma unroll
    for (int j = 0; j < 8; j++) {
        float v = acc[j];
        if (do_relu) v = fmaxf(v, 0.f);
        out[(size_t)(g0 + j) * Od + o] = v;
    }
}

// ---------------- final layer + log_softmax ----------------
__global__ void final_k(const float* __restrict__ w3, const float* __restrict__ b3,
                        float* __restrict__ out) {
    int g = threadIdx.x;
    if (g >= NG) return;
    float l0 = b3[0], l1 = b3[1];
    const float* h = d_h2 + (size_t)g * 384;
    for (int k = 0; k < 384; k++) {
        float v = h[k];
        l0 = fmaf(v, w3[k], l0);
        l1 = fmaf(v, w3[384 + k], l1);
    }
    float m = fmaxf(l0, l1);
    float lse = m + logf(expf(l0 - m) + expf(l1 - m));
    out[g * 2 + 0] = l0 - lse;
    out[g * 2 + 1] = l1 - lse;
}

extern "C" void kernel_launch(void* const* d_in, const int* in_sizes, int n_in,
                              void* d_out, int out_size) {
    const float* x      = (const float*)d_in[0];
    const int*   ei     = (const int*)d_in[1];
    const int*   batch  = (const int*)d_in[2];
    const float* w_rel  = (const float*)d_in[4];
    const float* b_rel  = (const float*)d_in[5];
    const float* w_root = (const float*)d_in[6];
    const float* n0g    = (const float*)d_in[7];
    const float* n0b    = (const float*)d_in[8];
    const float* lin_w  = (const float*)d_in[9];
    const float* lin_b  = (const float*)d_in[10];
    const float* bnh_g  = (const float*)d_in[11];
    const float* bnh_b  = (const float*)d_in[12];
    const float* bno_g  = (const float*)d_in[13];
    const float* bno_b  = (const float*)d_in[14];
    const float* w1     = (const float*)d_in[15];
    const float* b1     = (const float*)d_in[16];
    const float* w2     = (const float*)d_in[17];
    const float* b2     = (const float*)d_in[18];
    const float* w3     = (const float*)d_in[19];
    const float* b3     = (const float*)d_in[20];
    float* out = (float*)d_out;
    const int* row = ei;
    const int* col = ei + NE;

    float *p_neigh, *p_Xr, *p_H1, *p_H2, *p_stX, *p_scX, *p_shX;
    float *p_Hbn, *p_h1, *p_h2, *p_xr, *p_Hm;
    int *p_offc, *p_offr, *p_srcc, *p_srcr;
    cudaGetSymbolAddress((void**)&p_neigh, d_neigh);
    cudaGetSymbolAddress((void**)&p_Xr, d_Xr);
    cudaGetSymbolAddress((void**)&p_H1, d_H1);
    cudaGetSymbolAddress((void**)&p_H2, d_H2);
    cudaGetSymbolAddress((void**)&p_Hm, d_Hm);
    cudaGetSymbolAddress((void**)&p_stX, d_stX);
    cudaGetSymbolAddress((void**)&p_scX, d_scX);
    cudaGetSymbolAddress((void**)&p_shX, d_shX);
    cudaGetSymbolAddress((void**)&p_Hbn, d_Hbn);
    cudaGetSymbolAddress((void**)&p_h1, d_h1);
    cudaGetSymbolAddress((void**)&p_h2, d_h2);
    cudaGetSymbolAddress((void**)&p_xr, d_xr);
    cudaGetSymbolAddress((void**)&p_offc, d_offc);
    cudaGetSymbolAddress((void**)&p_offr, d_offr);
    cudaGetSymbolAddress((void**)&p_srcc, d_srcc);
    cudaGetSymbolAddress((void**)&p_srcr, d_srcr);

    cudaFuncSetAttribute(gemm_x_k, cudaFuncAttributeMaxDynamicSharedMemorySize, GSMEM);
    cudaFuncSetAttribute(gemm_hm_k, cudaFuncAttributeMaxDynamicSharedMemorySize, GSMEM);

    const int ROWBLK = (NN + 127) / 128;   // 391
    const int NODEBLK = (NN + 7) / 8;      // 6250

    // ---- CSR build + operand rounding ----
    init_k<<<(NN + 255) / 256, 256>>>();
    hist_k<<<(NE + 255) / 256, 256>>>(row, col);
    scan_k<<<2, SCAN_T>>>();
    fill_k<<<(NE + 255) / 256, 256>>>(row, col);
    round_copy_k<<<(NN * CDIM + 255) / 256, 256>>>(x, p_xr, NN * CDIM);
    round_weights_k<<<(CDIM * CDIM) / 256, 256>>>(w_rel, w_root);
    // neigh[n] = sum (dst=col) of x[src]  (stored tf32-rounded)
    spmm_csr_k<<<NODEBLK, 256>>>(x, p_neigh, p_offc, p_srcc, nullptr, nullptr);
    // Xr = tf32( neigh @ w_rel^T + x @ w_root^T + b_rel )
    gemm_x_k<<<ROWBLK, 256, GSMEM>>>(b_rel);
    stats2_k<<<800, 256>>>(p_Xr, 128, p_stX, 63);
    finalize_bnX_k<<<1, 128>>>(n0g, n0b);
    lin_transform_k<<<M3, 128>>>(lin_w, lin_b);
    // H1 = A·BN(Xr) (affine fused, rounded); H2 = A·H1 (rounded)
    spmm_csr_k<<<NODEBLK, 256>>>(p_Xr, p_H1, p_offr, p_srcr, p_scX, p_shX);
    spmm_csr_k<<<NODEBLK, 256>>>(p_H1, p_H2, p_offr, p_srcr, nullptr, nullptr);
    // masked block-lower-triangular lin GEMM (BN folded into weights)
    gemm_hm_k<<<dim3(ROWBLK, 3), 256, GSMEM>>>();
    // single-read per-graph pooling; bnh BN stats from per-graph sums
    pool_raw_k<<<NG, 384>>>(batch);
    stats_pool_k<<<3, 128>>>(bnh_g, bnh_b);
    emit_hcat_k<<<NG, 384>>>();
    bn_graphs_k<<<CAT / 128, 128>>>(bno_g, bno_b);
    mlp_k<<<dim3(768 / 128, NG / 8), 128, 8 * 1152 * sizeof(float)>>>(
        p_Hbn, 1152, w1, b1, p_h1, 768, 1);
    mlp_k<<<dim3(384 / 128, NG / 8), 128, 8 * 768 * sizeof(float)>>>(
        p_h1, 768, w2, b2, p_h2, 384, 1);
    final_k<<<1, 128>>>(w3, b3, out);
}

// round 15
// speedup vs baseline: 1.0058x; 1.0058x over previous
#include <cuda_runtime.h>
#include <math.h>
#include <stdint.h>

#define NN 50000
#define NE 600000
#define NG 128
#define CDIM 128
#define M3 384
#define CAT 1152
#define EPSB 1e-5f
#define SCAN_T 1024
#define AST 36                       // smem row stride (words)
#define GSMEM (4 * 128 * AST * 4)    // 2 stages x (A+W) x 128x36 words

// ---------------- static scratch (no allocations allowed) ----------------
__device__ float d_neigh[(size_t)NN * CDIM];
__device__ float d_Xr[(size_t)NN * CDIM];
__device__ float d_xr[(size_t)NN * CDIM];
__device__ float d_H1[(size_t)NN * CDIM];
__device__ float d_H2[(size_t)NN * CDIM];
__device__ float d_Hm[(size_t)NN * M3];
__device__ float d_wrelt[CDIM * CDIM];
__device__ float d_wroott[CDIM * CDIM];
__device__ float d_linwt[M3 * M3];
__device__ float d_linbt[M3];
__device__ float d_stX[2 * CDIM];
__device__ float d_scX[CDIM];
__device__ float d_shX[CDIM];
__device__ float d_scH[M3];
__device__ float d_shH[M3];
__device__ float d_gsum[NG * M3];
__device__ float d_gsq[NG * M3];
__device__ float d_gmax[NG * M3];
__device__ float d_gmin[NG * M3];
__device__ int   d_gcnt[NG];
__device__ float d_Hcat[NG * CAT];
__device__ float d_Hbn[NG * CAT];
__device__ float d_h1[NG * 768];
__device__ float d_h2[NG * 384];
// CSR scratch
__device__ int d_degc[NN], d_degr[NN];
__device__ int d_offc[NN + 1], d_offr[NN + 1];
__device__ int d_curc[NN], d_curr[NN];
__device__ int d_srcc[NE];
__device__ int d_srcr[NE];

// ---------------- tf32 helpers ----------------
__device__ __forceinline__ unsigned f2tf32(float v) {
    unsigned r;
    asm("cvt.rna.tf32.f32 %0, %1;" : "=r"(r) : "f"(v));
    return r;
}
__device__ __forceinline__ float rnd_tf32(float v) { return __uint_as_float(f2tf32(v)); }
__device__ __forceinline__ void mma_tf32(float* c, const unsigned* a, const unsigned* b) {
    asm volatile(
        "mma.sync.aligned.m16n8k8.row.col.f32.tf32.tf32.f32 "
        "{%0,%1,%2,%3}, {%4,%5,%6,%7}, {%8,%9}, {%0,%1,%2,%3};"
        : "+f"(c[0]), "+f"(c[1]), "+f"(c[2]), "+f"(c[3])
        : "r"(a[0]), "r"(a[1]), "r"(a[2]), "r"(a[3]), "r"(b[0]), "r"(b[1]));
}
// ---------------- cp.async helpers ----------------
__device__ __forceinline__ void cpa16(uint32_t saddr, const void* g, int bytes) {
    asm volatile("cp.async.cg.shared.global [%0], [%1], 16, %2;"
                 :: "r"(saddr), "l"(g), "r"(bytes));
}
__device__ __forceinline__ void cpa_commit() { asm volatile("cp.async.commit_group;"); }
__device__ __forceinline__ void cpa_wait1() { asm volatile("cp.async.wait_group 1;"); }
__device__ __forceinline__ void cpa_wait0() { asm volatile("cp.async.wait_group 0;"); }

// ---------------- init: zero degrees + stats accumulators ----------------
__global__ void init_k() {
    int i = blockIdx.x * blockDim.x + threadIdx.x;
    if (i < NN) { d_degc[i] = 0; d_degr[i] = 0; }
    if (i < 2 * CDIM) d_stX[i] = 0.f;
}

// ---------------- degree histogram ----------------
__global__ void hist_k(const int* __restrict__ row, const int* __restrict__ col) {
    int e = blockIdx.x * blockDim.x + threadIdx.x;
    if (e >= NE) return;
    atomicAdd(&d_degc[__ldg(col + e)], 1);
    atomicAdd(&d_degr[__ldg(row + e)], 1);
}

// ---------------- exclusive scan (single block per array) ----------------
__global__ void scan_k() {
    __shared__ int sm[SCAN_T];
    const int* deg = (blockIdx.x == 0) ? d_degc : d_degr;
    int* off = (blockIdx.x == 0) ? d_offc : d_offr;
    int* cur = (blockIdx.x == 0) ? d_curc : d_curr;
    int t = threadIdx.x;
    const int CH = (NN + SCAN_T - 1) / SCAN_T;
    int b = t * CH, e = min(b + CH, NN);
    int s = 0;
    for (int i = b; i < e; i++) s += deg[i];
    sm[t] = s;
    __syncthreads();
    for (int d = 1; d < SCAN_T; d <<= 1) {
        int u = (t >= d) ? sm[t - d] : 0;
        __syncthreads();
        sm[t] += u;
        __syncthreads();
    }
    int p = (t == 0) ? 0 : sm[t - 1];
    for (int i = b; i < e; i++) {
        off[i] = p;
        cur[i] = p;
        p += deg[i];
    }
    if (t == SCAN_T - 1) off[NN] = sm[SCAN_T - 1];
}

// ---------------- fill CSR edge lists ----------------
__global__ void fill_k(const int* __restrict__ row, const int* __restrict__ col) {
    int e = blockIdx.x * blockDim.x + threadIdx.x;
    if (e >= NE) return;
    int r = __ldg(row + e), c = __ldg(col + e);
    int pc = atomicAdd(&d_curc[c], 1);
    d_srcc[pc] = r;
    int pr = atomicAdd(&d_curr[r], 1);
    d_srcr[pr] = c;
}

// ---------------- round-copy (tf32 quantize) ----------------
__global__ void round_copy_k(const float* __restrict__ src, float* __restrict__ dst, int n) {
    int i = blockIdx.x * blockDim.x + threadIdx.x;
    if (i < n) dst[i] = rnd_tf32(__ldg(src + i));
}
__global__ void round_weights_k(const float* __restrict__ wrel, const float* __restrict__ wroot) {
    int i = blockIdx.x * blockDim.x + threadIdx.x;  // 0..16383
    d_wrelt[i] = rnd_tf32(__ldg(wrel + i));
    d_wroott[i] = rnd_tf32(__ldg(wroot + i));
}

// ---------------- CSR gather-accumulate (MLP-4 unrolled); stores tf32-rounded ----------------
__global__ void spmm_csr_k(const float* __restrict__ src, float* __restrict__ dst,
                           const int* __restrict__ off, const int* __restrict__ idx,
                           const float* __restrict__ sc, const float* __restrict__ sh) {
    int node = blockIdx.x * 8 + (threadIdx.x >> 5);
    if (node >= NN) return;
    int q = threadIdx.x & 31;
    int beg = __ldg(off + node), end = __ldg(off + node + 1);
    float4 acc = make_float4(0.f, 0.f, 0.f, 0.f);
    int e = beg;
    for (; e + 3 < end; e += 4) {
        int s0 = __ldg(idx + e), s1 = __ldg(idx + e + 1);
        int s2 = __ldg(idx + e + 2), s3 = __ldg(idx + e + 3);
        float4 v0 = __ldg((const float4*)src + (size_t)s0 * 32 + q);
        float4 v1 = __ldg((const float4*)src + (size_t)s1 * 32 + q);
        float4 v2 = __ldg((const float4*)src + (size_t)s2 * 32 + q);
        float4 v3 = __ldg((const float4*)src + (size_t)s3 * 32 + q);
        acc.x += (v0.x + v1.x) + (v2.x + v3.x);
        acc.y += (v0.y + v1.y) + (v2.y + v3.y);
        acc.z += (v0.z + v1.z) + (v2.z + v3.z);
        acc.w += (v0.w + v1.w) + (v2.w + v3.w);
    }
    for (; e < end; ++e) {
        int s0 = __ldg(idx + e);
        float4 v0 = __ldg((const float4*)src + (size_t)s0 * 32 + q);
        acc.x += v0.x; acc.y += v0.y; acc.z += v0.z; acc.w += v0.w;
    }
    if (sc) {
        float d = (float)(end - beg);
        float4 s4 = __ldg((const float4*)sc + q);
        float4 h4 = __ldg((const float4*)sh + q);
        acc.x = fmaf(acc.x, s4.x, h4.x * d);
        acc.y = fmaf(acc.y, s4.y, h4.y * d);
        acc.z = fmaf(acc.z, s4.z, h4.z * d);
        acc.w = fmaf(acc.w, s4.w, h4.w * d);
    }
    acc.x = rnd_tf32(acc.x); acc.y = rnd_tf32(acc.y);
    acc.z = rnd_tf32(acc.z); acc.w = rnd_tf32(acc.w);
    ((float4*)dst)[(size_t)node * 32 + q] = acc;
}

// ---------------- stage issue helper for async GEMM ----------------
__device__ __forceinline__ void gemm_issue_stage(
    const float* const* Ap, const float* const* Wp, int st, int ldw,
    int r0, int rrb, int kq, uint32_t sbase, int BUF) {
    const float* A = Ap[st >> 2];
    const float* W = Wp[st >> 2];
    int kb = (st & 3) * 32;
    uint32_t abase = sbase + (uint32_t)((st & 1) * BUF) * 4;
    uint32_t wbase = abase + 128 * AST * 4;
#pragma unroll
    for (int it = 0; it < 4; ++it) {
        int rr = rrb + it * 32;
        int r = r0 + rr;
        int ok = (r < NN);
        const float* ga = A + (size_t)(ok ? r : 0) * CDIM + kb + kq;
        cpa16(abase + (uint32_t)(rr * AST + kq) * 4, ga, ok ? 16 : 0);
        cpa16(wbase + (uint32_t)(rr * AST + kq) * 4, W + (size_t)rr * ldw + kb + kq, 16);
    }
    cpa_commit();
}

// ================= tf32 GEMM core, cp.async double-buffered =================
__device__ __forceinline__ void gemm_core_async(
    const float* const* Ap, const float* const* Wp, int nIn, int ldw,
    const float* __restrict__ bias, float* __restrict__ Cp, int ldc,
    int r0, int cbase, int round_primary, unsigned* smemu) {
    const int tx = threadIdx.x;
    const int lane = tx & 31;
    const int warp = tx >> 5;
    const int wr = (warp & 3) * 32;
    const int wc = (warp >> 2) * 64;
    const int g = lane >> 2;
    const int t4 = lane & 3;
    const int rrb = tx >> 3;        // 0..31
    const int kq = (tx & 7) * 4;    // 0..28
    const uint32_t sbase = (uint32_t)__cvta_generic_to_shared(smemu);
    const int BUF = 2 * 128 * AST;  // words per stage (A+W)

    float acc[2][8][4];
#pragma unroll
    for (int mi = 0; mi < 2; mi++)
#pragma unroll
        for (int ni = 0; ni < 8; ni++)
#pragma unroll
            for (int j = 0; j < 4; j++) acc[mi][ni][j] = 0.f;

    const int nSteps = nIn * 4;

    gemm_issue_stage(Ap, Wp, 0, ldw, r0, rrb, kq, sbase, BUF);
    for (int st = 0; st < nSteps; ++st) {
        if (st + 1 < nSteps) {
            gemm_issue_stage(Ap, Wp, st + 1, ldw, r0, rrb, kq, sbase, BUF);
            cpa_wait1();
        } else {
            cpa_wait0();
        }
        __syncthreads();
        const unsigned* Ab = smemu + (st & 1) * BUF;
        const unsigned* Wb = Ab + 128 * AST;
#pragma unroll
        for (int kk = 0; kk < 32; kk += 8) {
            unsigned a[2][4], b[8][2];
#pragma unroll
            for (int mi = 0; mi < 2; mi++) {
                int r = wr + mi * 16;
                a[mi][0] = Ab[(r + g) * AST + kk + t4];
                a[mi][1] = Ab[(r + g + 8) * AST + kk + t4];
                a[mi][2] = Ab[(r + g) * AST + kk + t4 + 4];
                a[mi][3] = Ab[(r + g + 8) * AST + kk + t4 + 4];
            }
#pragma unroll
            for (int ni = 0; ni < 8; ni++) {
                int n = wc + ni * 8 + g;
                b[ni][0] = Wb[n * AST + kk + t4];
                b[ni][1] = Wb[n * AST + kk + t4 + 4];
            }
#pragma unroll
            for (int mi = 0; mi < 2; mi++)
#pragma unroll
                for (int ni = 0; ni < 8; ni++)
                    mma_tf32(acc[mi][ni], a[mi], b[ni]);
        }
        __syncthreads();
    }

    // epilogue: bias, optional tf32 rounding, write
#pragma unroll
    for (int mi = 0; mi < 2; mi++) {
        int r1 = r0 + wr + mi * 16 + g;
        int r2 = r1 + 8;
#pragma unroll
        for (int ni = 0; ni < 8; ni++) {
            int cc = wc + ni * 8 + 2 * t4;
            float b0 = bias[cc], b1 = bias[cc + 1];
            if (r1 < NN) {
                float v0 = acc[mi][ni][0] + b0, v1 = acc[mi][ni][1] + b1;
                if (round_primary) { v0 = rnd_tf32(v0); v1 = rnd_tf32(v1); }
                Cp[(size_t)r1 * ldc + cbase + cc] = v0;
                Cp[(size_t)r1 * ldc + cbase + cc + 1] = v1;
            }
            if (r2 < NN) {
                float v2 = acc[mi][ni][2] + b0, v3 = acc[mi][ni][3] + b1;
                if (round_primary) { v2 = rnd_tf32(v2); v3 = rnd_tf32(v3); }
                Cp[(size_t)r2 * ldc + cbase + cc] = v2;
                Cp[(size_t)r2 * ldc + cbase + cc + 1] = v3;
            }
        }
    }
}

// Xr = tf32( neigh @ w_rel^T + xr @ w_root^T + b_rel )
__global__ void __launch_bounds__(256, 2) gemm_x_k(const float* __restrict__ bias) {
    extern __shared__ unsigned smemu[];
    const float* Ap[3] = {d_neigh, d_xr, nullptr};
    const float* Wp[3] = {d_wrelt, d_wroott, nullptr};
    gemm_core_async(Ap, Wp, 2, 128, bias, d_Xr, 128, blockIdx.x * 128, 0, 1, smemu);
}

// Hm strips with BN(X) folded into transformed weights/bias; j = jbase + blockIdx.y
__global__ void __launch_bounds__(256, 2) gemm_hm_k(int jbase) {
    extern __shared__ unsigned smemu[];
    int j = jbase + blockIdx.y;
    const float* Ap[3] = {d_Xr, d_H1, d_H2};
    const float* Wp[3];
    for (int i = 0; i < 3; i++)
        Wp[i] = d_linwt + (size_t)(j * 128) * M3 + i * 128;
    gemm_core_async(Ap, Wp, j + 1, M3, d_linbt + j * 128, d_Hm, M3,
                    blockIdx.x * 128, j * 128, 0, smemu);
}

// ---------------- per-column sum/sumsq over NN rows (X only) ----------------
__global__ void stats2_k(const float* __restrict__ A, int ncol, float* __restrict__ st,
                         int rows_per_blk) {
    __shared__ float sm[384 * 8];
    int n4 = ncol >> 2;
    int c4 = threadIdx.x % n4;
    int rl = threadIdx.x / n4;
    int rstep = blockDim.x / n4;
    int r0 = blockIdx.x * rows_per_blk;
    int rend = min(r0 + rows_per_blk, NN);
    float4 s = make_float4(0, 0, 0, 0), q = make_float4(0, 0, 0, 0);
    for (int r = r0 + rl; r < rend; r += rstep) {
        float4 v = __ldg((const float4*)(A + (size_t)r * ncol) + c4);
        s.x += v.x; s.y += v.y; s.z += v.z; s.w += v.w;
        q.x += v.x * v.x; q.y += v.y * v.y; q.z += v.z * v.z; q.w += v.w * v.w;
    }
    float* my = sm + threadIdx.x * 8;
    my[0] = s.x; my[1] = s.y; my[2] = s.z; my[3] = s.w;
    my[4] = q.x; my[5] = q.y; my[6] = q.z; my[7] = q.w;
    __syncthreads();
    if (threadIdx.x < (unsigned)n4) {
        float acc[8];
#pragma unroll
        for (int k = 0; k < 8; k++) acc[k] = 0.f;
        for (int j = 0; j < rstep; j++) {
            float* p = sm + (c4 + j * n4) * 8;
#pragma unroll
            for (int k = 0; k < 8; k++) acc[k] += p[k];
        }
#pragma unroll
        for (int k = 0; k < 4; k++) {
            atomicAdd(st + c4 * 4 + k, acc[k]);
            atomicAdd(st + ncol + c4 * 4 + k, acc[4 + k]);
        }
    }
}

// ---------------- finalize BN(X): stats -> per-channel scale/shift ----------------
__global__ void finalize_bnX_k(const float* __restrict__ gw, const float* __restrict__ gb) {
    int c = threadIdx.x;  // 128
    float mean = d_stX[c] * (1.f / NN);
    float var = d_stX[CDIM + c] * (1.f / NN) - mean * mean;
    float sc = gw[c] * rsqrtf(var + EPSB);
    d_scX[c] = sc;
    d_shX[c] = gb[c] - mean * sc;
}

// ---------------- fold BN(X) into lin weights/bias; tf32-round all of lin_w ----------------
__global__ void lin_transform_k(const float* __restrict__ lin_w, const float* __restrict__ lin_b) {
    __shared__ float red[128];
    int o = blockIdx.x;   // 0..383
    int t = threadIdx.x;  // 0..127
    const float* wrow = lin_w + (size_t)o * M3;
    float w0 = wrow[t];
    d_linwt[(size_t)o * M3 + t] = rnd_tf32(w0 * d_scX[t]);
    d_linwt[(size_t)o * M3 + 128 + t] = rnd_tf32(wrow[128 + t]);
    d_linwt[(size_t)o * M3 + 256 + t] = rnd_tf32(wrow[256 + t]);
    red[t] = d_shX[t] * w0;
    __syncthreads();
    for (int s2 = 64; s2 > 0; s2 >>= 1) {
        if (t < s2) red[t] += red[t + s2];
        __syncthreads();
    }
    if (t == 0) d_linbt[o] = lin_b[o] + red[0];
}

// ---------------- per-graph raw pooling over Hm: sum/sumsq/max/min ----------------
__global__ void pool_raw_k(const int* __restrict__ batch) {
    __shared__ float sm[384 * 16];
    int gph = blockIdx.x;
    int tx = threadIdx.x;
    int c4 = tx % 96;
    int rl = tx / 96;
    int lo = 0, hi = NN;
    while (lo < hi) { int m = (lo + hi) >> 1; if (batch[m] < gph) lo = m + 1; else hi = m; }
    int start = lo;
    lo = start; hi = NN;
    while (lo < hi) { int m = (lo + hi) >> 1; if (batch[m] < gph + 1) lo = m + 1; else hi = m; }
    int end = lo;

    float4 s = make_float4(0, 0, 0, 0), q = make_float4(0, 0, 0, 0);
    float4 mx = make_float4(-INFINITY, -INFINITY, -INFINITY, -INFINITY);
    float4 mn = make_float4(INFINITY, INFINITY, INFINITY, INFINITY);
    for (int r = start + rl; r < end; r += 4) {
        float4 v = __ldg((const float4*)(d_Hm + (size_t)r * M3) + c4);
        s.x += v.x; s.y += v.y; s.z += v.z; s.w += v.w;
        q.x += v.x * v.x; q.y += v.y * v.y; q.z += v.z * v.z; q.w += v.w * v.w;
        mx.x = fmaxf(mx.x, v.x); mx.y = fmaxf(mx.y, v.y);
        mx.z = fmaxf(mx.z, v.z); mx.w = fmaxf(mx.w, v.w);
        mn.x = fminf(mn.x, v.x); mn.y = fminf(mn.y, v.y);
        mn.z = fminf(mn.z, v.z); mn.w = fminf(mn.w, v.w);
    }
    float* my = sm + tx * 16;
    my[0] = s.x; my[1] = s.y; my[2] = s.z; my[3] = s.w;
    my[4] = q.x; my[5] = q.y; my[6] = q.z; my[7] = q.w;
    my[8] = mx.x; my[9] = mx.y; my[10] = mx.z; my[11] = mx.w;
    my[12] = mn.x; my[13] = mn.y; my[14] = mn.z; my[15] = mn.w;
    __syncthreads();
    if (rl == 0) {  // tx < 96
        float a[16];
#pragma unroll
        for (int k = 0; k < 16; k++) a[k] = my[k];
        for (int j = 1; j < 4; j++) {
            float* p = sm + (tx + j * 96) * 16;
#pragma unroll
            for (int k = 0; k < 4; k++) {
                a[k] += p[k];
                a[4 + k] += p[4 + k];
                a[8 + k] = fmaxf(a[8 + k], p[8 + k]);
                a[12 + k] = fminf(a[12 + k], p[12 + k]);
            }
        }
#pragma unroll
        for (int k = 0; k < 4; k++) {
            int col = c4 * 4 + k;
            d_gsum[gph * M3 + col] = a[k];
            d_gsq[gph * M3 + col] = a[4 + k];
            d_gmax[gph * M3 + col] = a[8 + k];
            d_gmin[gph * M3 + col] = a[12 + k];
        }
    }
    if (tx == 0) d_gcnt[gph] = end - start;
}

// ---------------- bnh BN scale/shift from per-graph sums ----------------
__global__ void stats_pool_k(const float* __restrict__ gw, const float* __restrict__ gb) {
    int c = blockIdx.x * 128 + threadIdx.x;  // 0..383
    float ts = 0.f, tq = 0.f;
    for (int g2 = 0; g2 < NG; g2++) {
        ts += d_gsum[g2 * M3 + c];
        tq += d_gsq[g2 * M3 + c];
    }
    float mean = ts * (1.f / NN);
    float var = tq * (1.f / NN) - mean * mean;
    float sc = gw[c] * rsqrtf(var + EPSB);
    d_scH[c] = sc;
    d_shH[c] = gb[c] - mean * sc;
}

// ---------------- emit Hcat (parallel over graphs) ----------------
__global__ void emit_hcat_k() {
    int g2 = blockIdx.x;      // graph
    int c = threadIdx.x;      // 0..383
    float sc = d_scH[c], sh = d_shH[c];
    int cnt = d_gcnt[g2];
    float add = sc * d_gsum[g2 * M3 + c] + sh * (float)cnt;
    float avg = (cnt > 0) ? add / (float)cnt : 0.f;
    float mxv = 0.f;
    if (cnt > 0)
        mxv = (sc >= 0.f) ? fmaf(sc, d_gmax[g2 * M3 + c], sh)
                          : fmaf(sc, d_gmin[g2 * M3 + c], sh);
    d_Hcat[(size_t)g2 * CAT + c] = avg;
    d_Hcat[(size_t)g2 * CAT + 384 + c] = add;
    d_Hcat[(size_t)g2 * CAT + 768 + c] = mxv;
}

// ---------------- BN over graphs ----------------
__global__ void bn_graphs_k(const float* __restrict__ gw, const float* __restrict__ gb) {
    int c = blockIdx.x * blockDim.x + threadIdx.x;
    if (c >= CAT) return;
    float s = 0.f, ss = 0.f;
    for (int r = 0; r < NG; r++) { float v = d_Hcat[r * CAT + c]; s += v; ss += v * v; }
    float mean = s * (1.f / NG);
    float var = ss * (1.f / NG) - mean * mean;
    float sc = gw[c] * rsqrtf(var + EPSB);
    float sh = gb[c] - mean * sc;
    for (int r = 0; r < NG; r++) d_Hbn[r * CAT + c] = fmaf(d_Hcat[r * CAT + c], sc, sh);
}

// ---------------- small dense layer ----------------
__global__ void mlp_k(const float* __restrict__ A, int Kd,
                      const float* __restrict__ W, const float* __restrict__ bias,
                      float* __restrict__ out, int Od, int do_relu) {
    extern __shared__ float sA[];
    int g0 = blockIdx.y * 8;
    for (int idx = threadIdx.x; idx < 8 * Kd; idx += blockDim.x)
        sA[idx] = A[(size_t)(g0 + idx / Kd) * Kd + (idx % Kd)];
    __syncthreads();
    int o = blockIdx.x * blockDim.x + threadIdx.x;
    float bb = bias[o];
    float acc[8];
#pragma unroll
    for (int j = 0; j < 8; j++) acc[j] = bb;
    const float* wr = W + (size_t)o * Kd;
    for (int k = 0; k < Kd; k++) {
        float w = wr[k];
#pragma unroll
        for (int j = 0; j < 8; j++) acc[j] = fmaf(w, sA[j * Kd + k], acc[j]);
    }
#pragma unroll
    for (int j = 0; j < 8; j++) {
        float v = acc[j];
        if (do_relu) v = fmaxf(v, 0.f);
        out[(size_t)(g0 + j) * Od + o] = v;
    }
}

// ---------------- final layer + log_softmax ----------------
__global__ void final_k(const float* __restrict__ w3, const float* __restrict__ b3,
                        float* __restrict__ out) {
    int g = threadIdx.x;
    if (g >= NG) return;
    float l0 = b3[0], l1 = b3[1];
    const float* h = d_h2 + (size_t)g * 384;
    for (int k = 0; k < 384; k++) {
        float v = h[k];
        l0 = fmaf(v, w3[k], l0);
        l1 = fmaf(v, w3[384 + k], l1);
    }
    float m = fmaxf(l0, l1);
    float lse = m + logf(expf(l0 - m) + expf(l1 - m));
    out[g * 2 + 0] = l0 - lse;
    out[g * 2 + 1] = l1 - lse;
}

extern "C" void kernel_launch(void* const* d_in, const int* in_sizes, int n_in,
                              void* d_out, int out_size) {
    const float* x      = (const float*)d_in[0];
    const int*   ei     = (const int*)d_in[1];
    const int*   batch  = (const int*)d_in[2];
    const float* w_rel  = (const float*)d_in[4];
    const float* b_rel  = (const float*)d_in[5];
    const float* w_root = (const float*)d_in[6];
    const float* n0g    = (const float*)d_in[7];
    const float* n0b    = (const float*)d_in[8];
    const float* lin_w  = (const float*)d_in[9];
    const float* lin_b  = (const float*)d_in[10];
    const float* bnh_g  = (const float*)d_in[11];
    const float* bnh_b  = (const float*)d_in[12];
    const float* bno_g  = (const float*)d_in[13];
    const float* bno_b  = (const float*)d_in[14];
    const float* w1     = (const float*)d_in[15];
    const float* b1     = (const float*)d_in[16];
    const float* w2     = (const float*)d_in[17];
    const float* b2     = (const float*)d_in[18];
    const float* w3     = (const float*)d_in[19];
    const float* b3     = (const float*)d_in[20];
    float* out = (float*)d_out;
    const int* row = ei;
    const int* col = ei + NE;

    float *p_neigh, *p_Xr, *p_H1, *p_H2, *p_stX, *p_scX, *p_shX;
    float *p_Hbn, *p_h1, *p_h2, *p_xr, *p_Hm;
    int *p_offc, *p_offr, *p_srcc, *p_srcr;
    cudaGetSymbolAddress((void**)&p_neigh, d_neigh);
    cudaGetSymbolAddress((void**)&p_Xr, d_Xr);
    cudaGetSymbolAddress((void**)&p_H1, d_H1);
    cudaGetSymbolAddress((void**)&p_H2, d_H2);
    cudaGetSymbolAddress((void**)&p_Hm, d_Hm);
    cudaGetSymbolAddress((void**)&p_stX, d_stX);
    cudaGetSymbolAddress((void**)&p_scX, d_scX);
    cudaGetSymbolAddress((void**)&p_shX, d_shX);
    cudaGetSymbolAddress((void**)&p_Hbn, d_Hbn);
    cudaGetSymbolAddress((void**)&p_h1, d_h1);
    cudaGetSymbolAddress((void**)&p_h2, d_h2);
    cudaGetSymbolAddress((void**)&p_xr, d_xr);
    cudaGetSymbolAddress((void**)&p_offc, d_offc);
    cudaGetSymbolAddress((void**)&p_offr, d_offr);
    cudaGetSymbolAddress((void**)&p_srcc, d_srcc);
    cudaGetSymbolAddress((void**)&p_srcr, d_srcr);

    cudaFuncSetAttribute(gemm_x_k, cudaFuncAttributeMaxDynamicSharedMemorySize, GSMEM);
    cudaFuncSetAttribute(gemm_hm_k, cudaFuncAttributeMaxDynamicSharedMemorySize, GSMEM);

    // one-time side stream + events (same captured work every call)
    static cudaStream_t s2 = nullptr;
    static cudaEvent_t evF1 = nullptr, evJ1 = nullptr, evF2 = nullptr, evJ2 = nullptr;
    if (!s2) {
        cudaStreamCreateWithFlags(&s2, cudaStreamNonBlocking);
        cudaEventCreateWithFlags(&evF1, cudaEventDisableTiming);
        cudaEventCreateWithFlags(&evJ1, cudaEventDisableTiming);
        cudaEventCreateWithFlags(&evF2, cudaEventDisableTiming);
        cudaEventCreateWithFlags(&evJ2, cudaEventDisableTiming);
    }

    const int ROWBLK = (NN + 127) / 128;   // 391
    const int NODEBLK = (NN + 7) / 8;      // 6250

    // ---- fork 1: rounding passes on s2, CSR build on main ----
    cudaEventRecord(evF1, 0);
    cudaStreamWaitEvent(s2, evF1, 0);
    round_copy_k<<<(NN * CDIM + 255) / 256, 256, 0, s2>>>(x, p_xr, NN * CDIM);
    round_weights_k<<<(CDIM * CDIM) / 256, 256, 0, s2>>>(w_rel, w_root);
    cudaEventRecord(evJ1, s2);

    init_k<<<(NN + 255) / 256, 256>>>();
    hist_k<<<(NE + 255) / 256, 256>>>(row, col);
    scan_k<<<2, SCAN_T>>>();
    fill_k<<<(NE + 255) / 256, 256>>>(row, col);
    // neigh[n] = sum (dst=col) of x[src]  (stored tf32-rounded)
    spmm_csr_k<<<NODEBLK, 256>>>(x, p_neigh, p_offc, p_srcc, nullptr, nullptr);
    cudaStreamWaitEvent(0, evJ1, 0);  // need xr + rounded weights
    // Xr = tf32( neigh @ w_rel^T + x @ w_root^T + b_rel )
    gemm_x_k<<<ROWBLK, 256, GSMEM>>>(b_rel);
    stats2_k<<<400, 256>>>(p_Xr, 128, p_stX, 125);
    finalize_bnX_k<<<1, 128>>>(n0g, n0b);
    lin_transform_k<<<M3, 128>>>(lin_w, lin_b);

    // ---- fork 2: Hm strip 0 (needs only Xr) on s2, H1/H2 spmm on main ----
    cudaEventRecord(evF2, 0);
    cudaStreamWaitEvent(s2, evF2, 0);
    gemm_hm_k<<<dim3(ROWBLK, 1), 256, GSMEM, s2>>>(0);
    cudaEventRecord(evJ2, s2);

    spmm_csr_k<<<NODEBLK, 256>>>(p_Xr, p_H1, p_offr, p_srcr, p_scX, p_shX);
    spmm_csr_k<<<NODEBLK, 256>>>(p_H1, p_H2, p_offr, p_srcr, nullptr, nullptr);
    gemm_hm_k<<<dim3(ROWBLK, 2), 256, GSMEM>>>(1);
    cudaStreamWaitEvent(0, evJ2, 0);  // strip 0 must finish before pooling

    // single-read per-graph pooling; bnh BN stats from per-graph sums
    pool_raw_k<<<NG, 384>>>(batch);
    stats_pool_k<<<3, 128>>>(bnh_g, bnh_b);
    emit_hcat_k<<<NG, 384>>>();
    bn_graphs_k<<<CAT / 128, 128>>>(bno_g, bno_b);
    mlp_k<<<dim3(768 / 128, NG / 8), 128, 8 * 1152 * sizeof(float)>>>(
        p_Hbn, 1152, w1, b1, p_h1, 768, 1);
    mlp_k<<<dim3(384 / 128, NG / 8), 128, 8 * 768 * sizeof(float)>>>(
        p_h1, 768, w2, b2, p_h2, 384, 1);
    final_k<<<1, 128>>>(w3, b3, out);
}

// round 16
// speedup vs baseline: 1.0363x; 1.0304x over previous
#include <cuda_runtime.h>
#include <math.h>
#include <stdint.h>

#define NN 50000
#define NE 600000
#define NG 128
#define CDIM 128
#define M3 384
#define CAT 1152
#define EPSB 1e-5f
#define SCAN_T 1024
#define AST 36                       // smem row stride (words)
#define GSMEM (4 * 128 * AST * 4)    // 2 stages x (A+W) x 128x36 words = 73728 B

// ---------------- static scratch (no allocations allowed) ----------------
__device__ float d_neigh[(size_t)NN * CDIM];
__device__ float d_Xr[(size_t)NN * CDIM];
__device__ float d_xr[(size_t)NN * CDIM];
__device__ float d_H1[(size_t)NN * CDIM];
__device__ float d_H2[(size_t)NN * CDIM];
__device__ float d_wrelt[CDIM * CDIM];
__device__ float d_wroott[CDIM * CDIM];
__device__ float d_linwt[M3 * M3];
__device__ float d_linbt[M3];
__device__ float d_stX[2 * CDIM];
__device__ float d_scX[CDIM];
__device__ float d_shX[CDIM];
__device__ float d_scH[M3];
__device__ float d_shH[M3];
__device__ float d_gsum[NG * M3];
__device__ float d_gsq[NG * M3];
__device__ float d_gmax[NG * M3];
__device__ float d_gmin[NG * M3];
__device__ int   d_gcnt[NG];
__device__ float d_Hcat[NG * CAT];
__device__ float d_Hbn[NG * CAT];
__device__ float d_h1[NG * 768];
__device__ float d_h2[NG * 384];
// CSR scratch
__device__ int d_degc[NN], d_degr[NN];
__device__ int d_offc[NN + 1], d_offr[NN + 1];
__device__ int d_curc[NN], d_curr[NN];
__device__ int d_srcc[NE];
__device__ int d_srcr[NE];

// ---------------- tf32 helpers ----------------
__device__ __forceinline__ unsigned f2tf32(float v) {
    unsigned r;
    asm("cvt.rna.tf32.f32 %0, %1;" : "=r"(r) : "f"(v));
    return r;
}
__device__ __forceinline__ float rnd_tf32(float v) { return __uint_as_float(f2tf32(v)); }
__device__ __forceinline__ void mma_tf32(float* c, const unsigned* a, const unsigned* b) {
    asm volatile(
        "mma.sync.aligned.m16n8k8.row.col.f32.tf32.tf32.f32 "
        "{%0,%1,%2,%3}, {%4,%5,%6,%7}, {%8,%9}, {%0,%1,%2,%3};"
        : "+f"(c[0]), "+f"(c[1]), "+f"(c[2]), "+f"(c[3])
        : "r"(a[0]), "r"(a[1]), "r"(a[2]), "r"(a[3]), "r"(b[0]), "r"(b[1]));
}
// ---------------- float atomic max/min (sign-split trick) ----------------
__device__ __forceinline__ void atomicMaxF(float* a, float v) {
    if (v >= 0.f) atomicMax((int*)a, __float_as_int(v));
    else atomicMin((unsigned*)a, __float_as_uint(v));
}
__device__ __forceinline__ void atomicMinF(float* a, float v) {
    if (v >= 0.f) atomicMin((int*)a, __float_as_int(v));
    else atomicMax((unsigned*)a, __float_as_uint(v));
}
// ---------------- cp.async helpers ----------------
__device__ __forceinline__ void cpa16(uint32_t saddr, const void* g, int bytes) {
    asm volatile("cp.async.cg.shared.global [%0], [%1], 16, %2;"
                 :: "r"(saddr), "l"(g), "r"(bytes));
}
__device__ __forceinline__ void cpa_commit() { asm volatile("cp.async.commit_group;"); }
__device__ __forceinline__ void cpa_wait1() { asm volatile("cp.async.wait_group 1;"); }
__device__ __forceinline__ void cpa_wait0() { asm volatile("cp.async.wait_group 0;"); }

// ---------------- init: degrees, stats, pool accumulators ----------------
__global__ void init_k() {
    int i = blockIdx.x * blockDim.x + threadIdx.x;
    if (i < NN) { d_degc[i] = 0; d_degr[i] = 0; }
    if (i < 2 * CDIM) d_stX[i] = 0.f;
    if (i < NG * M3) {
        d_gsum[i] = 0.f;
        d_gsq[i] = 0.f;
        d_gmax[i] = -INFINITY;
        d_gmin[i] = INFINITY;
    }
}

// ---------------- degree histogram ----------------
__global__ void hist_k(const int* __restrict__ row, const int* __restrict__ col) {
    int e = blockIdx.x * blockDim.x + threadIdx.x;
    if (e >= NE) return;
    atomicAdd(&d_degc[__ldg(col + e)], 1);
    atomicAdd(&d_degr[__ldg(row + e)], 1);
}

// ---------------- exclusive scan (single block per array) ----------------
__global__ void scan_k() {
    __shared__ int sm[SCAN_T];
    const int* deg = (blockIdx.x == 0) ? d_degc : d_degr;
    int* off = (blockIdx.x == 0) ? d_offc : d_offr;
    int* cur = (blockIdx.x == 0) ? d_curc : d_curr;
    int t = threadIdx.x;
    const int CH = (NN + SCAN_T - 1) / SCAN_T;
    int b = t * CH, e = min(b + CH, NN);
    int s = 0;
    for (int i = b; i < e; i++) s += deg[i];
    sm[t] = s;
    __syncthreads();
    for (int d = 1; d < SCAN_T; d <<= 1) {
        int u = (t >= d) ? sm[t - d] : 0;
        __syncthreads();
        sm[t] += u;
        __syncthreads();
    }
    int p = (t == 0) ? 0 : sm[t - 1];
    for (int i = b; i < e; i++) {
        off[i] = p;
        cur[i] = p;
        p += deg[i];
    }
    if (t == SCAN_T - 1) off[NN] = sm[SCAN_T - 1];
}

// ---------------- fill CSR edge lists ----------------
__global__ void fill_k(const int* __restrict__ row, const int* __restrict__ col) {
    int e = blockIdx.x * blockDim.x + threadIdx.x;
    if (e >= NE) return;
    int r = __ldg(row + e), c = __ldg(col + e);
    int pc = atomicAdd(&d_curc[c], 1);
    d_srcc[pc] = r;
    int pr = atomicAdd(&d_curr[r], 1);
    d_srcr[pr] = c;
}

// ---------------- per-graph node counts (binary search on sorted batch) ----------------
__global__ void gcnt_k(const int* __restrict__ batch) {
    int g = threadIdx.x;  // 0..127
    int lo = 0, hi = NN;
    while (lo < hi) { int m = (lo + hi) >> 1; if (batch[m] < g) lo = m + 1; else hi = m; }
    int start = lo;
    lo = start; hi = NN;
    while (lo < hi) { int m = (lo + hi) >> 1; if (batch[m] < g + 1) lo = m + 1; else hi = m; }
    d_gcnt[g] = lo - start;
}

// ---------------- round-copy (tf32 quantize) ----------------
__global__ void round_copy_k(const float* __restrict__ src, float* __restrict__ dst, int n) {
    int i = blockIdx.x * blockDim.x + threadIdx.x;
    if (i < n) dst[i] = rnd_tf32(__ldg(src + i));
}
__global__ void round_weights_k(const float* __restrict__ wrel, const float* __restrict__ wroot) {
    int i = blockIdx.x * blockDim.x + threadIdx.x;  // 0..16383
    d_wrelt[i] = rnd_tf32(__ldg(wrel + i));
    d_wroott[i] = rnd_tf32(__ldg(wroot + i));
}

// ---------------- CSR gather-accumulate (MLP-4 unrolled); stores tf32-rounded ----------------
__global__ void spmm_csr_k(const float* __restrict__ src, float* __restrict__ dst,
                           const int* __restrict__ off, const int* __restrict__ idx,
                           const float* __restrict__ sc, const float* __restrict__ sh) {
    int node = blockIdx.x * 8 + (threadIdx.x >> 5);
    if (node >= NN) return;
    int q = threadIdx.x & 31;
    int beg = __ldg(off + node), end = __ldg(off + node + 1);
    float4 acc = make_float4(0.f, 0.f, 0.f, 0.f);
    int e = beg;
    for (; e + 3 < end; e += 4) {
        int s0 = __ldg(idx + e), s1 = __ldg(idx + e + 1);
        int s2 = __ldg(idx + e + 2), s3 = __ldg(idx + e + 3);
        float4 v0 = __ldg((const float4*)src + (size_t)s0 * 32 + q);
        float4 v1 = __ldg((const float4*)src + (size_t)s1 * 32 + q);
        float4 v2 = __ldg((const float4*)src + (size_t)s2 * 32 + q);
        float4 v3 = __ldg((const float4*)src + (size_t)s3 * 32 + q);
        acc.x += (v0.x + v1.x) + (v2.x + v3.x);
        acc.y += (v0.y + v1.y) + (v2.y + v3.y);
        acc.z += (v0.z + v1.z) + (v2.z + v3.z);
        acc.w += (v0.w + v1.w) + (v2.w + v3.w);
    }
    for (; e < end; ++e) {
        int s0 = __ldg(idx + e);
        float4 v0 = __ldg((const float4*)src + (size_t)s0 * 32 + q);
        acc.x += v0.x; acc.y += v0.y; acc.z += v0.z; acc.w += v0.w;
    }
    if (sc) {
        float d = (float)(end - beg);
        float4 s4 = __ldg((const float4*)sc + q);
        float4 h4 = __ldg((const float4*)sh + q);
        acc.x = fmaf(acc.x, s4.x, h4.x * d);
        acc.y = fmaf(acc.y, s4.y, h4.y * d);
        acc.z = fmaf(acc.z, s4.z, h4.z * d);
        acc.w = fmaf(acc.w, s4.w, h4.w * d);
    }
    acc.x = rnd_tf32(acc.x); acc.y = rnd_tf32(acc.y);
    acc.z = rnd_tf32(acc.z); acc.w = rnd_tf32(acc.w);
    ((float4*)dst)[(size_t)node * 32 + q] = acc;
}

// ---------------- stage issue helper for async GEMM ----------------
__device__ __forceinline__ void gemm_issue_stage(
    const float* const* Ap, const float* const* Wp, int st, int ldw,
    int r0, int rrb, int kq, uint32_t sbase, int BUF) {
    const float* A = Ap[st >> 2];
    const float* W = Wp[st >> 2];
    int kb = (st & 3) * 32;
    uint32_t abase = sbase + (uint32_t)((st & 1) * BUF) * 4;
    uint32_t wbase = abase + 128 * AST * 4;
#pragma unroll
    for (int it = 0; it < 4; ++it) {
        int rr = rrb + it * 32;
        int r = r0 + rr;
        int ok = (r < NN);
        const float* ga = A + (size_t)(ok ? r : 0) * CDIM + kb + kq;
        cpa16(abase + (uint32_t)(rr * AST + kq) * 4, ga, ok ? 16 : 0);
        cpa16(wbase + (uint32_t)(rr * AST + kq) * 4, W + (size_t)rr * ldw + kb + kq, 16);
    }
    cpa_commit();
}

// ================= tf32 GEMM core, cp.async double-buffered =================
// pool_batch == nullptr : normal epilogue writing Cp (optionally tf32-rounded)
// pool_batch != nullptr : pooling epilogue — per-graph sum/sumsq/max/min atomics
__device__ __forceinline__ void gemm_core_async(
    const float* const* Ap, const float* const* Wp, int nIn, int ldw,
    const float* __restrict__ bias, float* __restrict__ Cp, int ldc,
    int r0, int cbase, int round_primary, const int* __restrict__ pool_batch,
    unsigned* smemu) {
    const int tx = threadIdx.x;
    const int lane = tx & 31;
    const int warp = tx >> 5;
    const int wr = (warp & 3) * 32;
    const int wc = (warp >> 2) * 64;
    const int g = lane >> 2;
    const int t4 = lane & 3;
    const int rrb = tx >> 3;        // 0..31
    const int kq = (tx & 7) * 4;    // 0..28
    const uint32_t sbase = (uint32_t)__cvta_generic_to_shared(smemu);
    const int BUF = 2 * 128 * AST;  // words per stage (A+W)

    float acc[2][8][4];
#pragma unroll
    for (int mi = 0; mi < 2; mi++)
#pragma unroll
        for (int ni = 0; ni < 8; ni++)
#pragma unroll
            for (int j = 0; j < 4; j++) acc[mi][ni][j] = 0.f;

    const int nSteps = nIn * 4;

    gemm_issue_stage(Ap, Wp, 0, ldw, r0, rrb, kq, sbase, BUF);
    for (int st = 0; st < nSteps; ++st) {
        if (st + 1 < nSteps) {
            gemm_issue_stage(Ap, Wp, st + 1, ldw, r0, rrb, kq, sbase, BUF);
            cpa_wait1();
        } else {
            cpa_wait0();
        }
        __syncthreads();
        const unsigned* Ab = smemu + (st & 1) * BUF;
        const unsigned* Wb = Ab + 128 * AST;
#pragma unroll
        for (int kk = 0; kk < 32; kk += 8) {
            unsigned a[2][4], b[8][2];
#pragma unroll
            for (int mi = 0; mi < 2; mi++) {
                int r = wr + mi * 16;
                a[mi][0] = Ab[(r + g) * AST + kk + t4];
                a[mi][1] = Ab[(r + g + 8) * AST + kk + t4];
                a[mi][2] = Ab[(r + g) * AST + kk + t4 + 4];
                a[mi][3] = Ab[(r + g + 8) * AST + kk + t4 + 4];
            }
#pragma unroll
            for (int ni = 0; ni < 8; ni++) {
                int n = wc + ni * 8 + g;
                b[ni][0] = Wb[n * AST + kk + t4];
                b[ni][1] = Wb[n * AST + kk + t4 + 4];
            }
#pragma unroll
            for (int mi = 0; mi < 2; mi++)
#pragma unroll
                for (int ni = 0; ni < 8; ni++)
                    mma_tf32(acc[mi][ni], a[mi], b[ni]);
        }
        __syncthreads();
    }

    if (!pool_batch) {
        // normal epilogue: bias, optional tf32 rounding, write
#pragma unroll
        for (int mi = 0; mi < 2; mi++) {
            int r1 = r0 + wr + mi * 16 + g;
            int r2 = r1 + 8;
#pragma unroll
            for (int ni = 0; ni < 8; ni++) {
                int cc = wc + ni * 8 + 2 * t4;
                float b0 = bias[cc], b1 = bias[cc + 1];
                if (r1 < NN) {
                    float v0 = acc[mi][ni][0] + b0, v1 = acc[mi][ni][1] + b1;
                    if (round_primary) { v0 = rnd_tf32(v0); v1 = rnd_tf32(v1); }
                    Cp[(size_t)r1 * ldc + cbase + cc] = v0;
                    Cp[(size_t)r1 * ldc + cbase + cc + 1] = v1;
                }
                if (r2 < NN) {
                    float v2 = acc[mi][ni][2] + b0, v3 = acc[mi][ni][3] + b1;
                    if (round_primary) { v2 = rnd_tf32(v2); v3 = rnd_tf32(v3); }
                    Cp[(size_t)r2 * ldc + cbase + cc] = v2;
                    Cp[(size_t)r2 * ldc + cbase + cc + 1] = v3;
                }
            }
        }
        return;
    }

    // pooling epilogue: stage tile in smem (stride 129), segment-reduce per column
    float* sv = (float*)smemu;              // 128 x 129 floats = 16512 words
    int* sbatch = (int*)(smemu + 16512);    // 128 ints
#pragma unroll
    for (int mi = 0; mi < 2; mi++) {
        int lr1 = wr + mi * 16 + g;
        int lr2 = lr1 + 8;
#pragma unroll
        for (int ni = 0; ni < 8; ni++) {
            int cc = wc + ni * 8 + 2 * t4;
            float b0 = bias[cc], b1 = bias[cc + 1];
            sv[lr1 * 129 + cc] = acc[mi][ni][0] + b0;
            sv[lr1 * 129 + cc + 1] = acc[mi][ni][1] + b1;
            sv[lr2 * 129 + cc] = acc[mi][ni][2] + b0;
            sv[lr2 * 129 + cc + 1] = acc[mi][ni][3] + b1;
        }
    }
    if (tx < 128) sbatch[tx] = (r0 + tx < NN) ? __ldg(pool_batch + r0 + tx) : -1;
    __syncthreads();
    if (tx < 128) {
        int c = tx;
        float s = 0.f, q = 0.f, mx = 0.f, mn = 0.f;
        int cur = -1;
        for (int r = 0; r < 128; ++r) {
            int bg = sbatch[r];
            if (bg < 0) break;
            float v = sv[r * 129 + c];
            if (bg != cur) {
                if (cur >= 0) {
                    atomicAdd(&d_gsum[cur * M3 + cbase + c], s);
                    atomicAdd(&d_gsq[cur * M3 + cbase + c], q);
                    atomicMaxF(&d_gmax[cur * M3 + cbase + c], mx);
                    atomicMinF(&d_gmin[cur * M3 + cbase + c], mn);
                }
                cur = bg; s = v; q = v * v; mx = v; mn = v;
            } else {
                s += v; q += v * v;
                mx = fmaxf(mx, v); mn = fminf(mn, v);
            }
        }
        if (cur >= 0) {
            atomicAdd(&d_gsum[cur * M3 + cbase + c], s);
            atomicAdd(&d_gsq[cur * M3 + cbase + c], q);
            atomicMaxF(&d_gmax[cur * M3 + cbase + c], mx);
            atomicMinF(&d_gmin[cur * M3 + cbase + c], mn);
        }
    }
}

// Xr = tf32( neigh @ w_rel^T + xr @ w_root^T + b_rel )
__global__ void __launch_bounds__(256, 2) gemm_x_k(const float* __restrict__ bias) {
    extern __shared__ unsigned smemu[];
    const float* Ap[3] = {d_neigh, d_xr, nullptr};
    const float* Wp[3] = {d_wrelt, d_wroott, nullptr};
    gemm_core_async(Ap, Wp, 2, 128, bias, d_Xr, 128, blockIdx.x * 128, 0, 1,
                    nullptr, smemu);
}

// Hm strips, BN folded into weights; pooling fused into epilogue (no Hm tensor)
__global__ void __launch_bounds__(256, 2) gemm_hm_k(const int* __restrict__ batch) {
    extern __shared__ unsigned smemu[];
    int j = blockIdx.y;
    const float* Ap[3] = {d_Xr, d_H1, d_H2};
    const float* Wp[3];
    for (int i = 0; i < 3; i++)
        Wp[i] = d_linwt + (size_t)(j * 128) * M3 + i * 128;
    gemm_core_async(Ap, Wp, j + 1, M3, d_linbt + j * 128, nullptr, M3,
                    blockIdx.x * 128, j * 128, 0, batch, smemu);
}

// ---------------- per-column sum/sumsq over NN rows (X only) ----------------
__global__ void stats2_k(const float* __restrict__ A, int ncol, float* __restrict__ st,
                         int rows_per_blk) {
    __shared__ float sm[384 * 8];
    int n4 = ncol >> 2;
    int c4 = threadIdx.x % n4;
    int rl = threadIdx.x / n4;
    int rstep = blockDim.x / n4;
    int r0 = blockIdx.x * rows_per_blk;
    int rend = min(r0 + rows_per_blk, NN);
    float4 s = make_float4(0, 0, 0, 0), q = make_float4(0, 0, 0, 0);
    for (int r = r0 + rl; r < rend; r += rstep) {
        float4 v = __ldg((const float4*)(A + (size_t)r * ncol) + c4);
        s.x += v.x; s.y += v.y; s.z += v.z; s.w += v.w;
        q.x += v.x * v.x; q.y += v.y * v.y; q.z += v.z * v.z; q.w += v.w * v.w;
    }
    float* my = sm + threadIdx.x * 8;
    my[0] = s.x; my[1] = s.y; my[2] = s.z; my[3] = s.w;
    my[4] = q.x; my[5] = q.y; my[6] = q.z; my[7] = q.w;
    __syncthreads();
    if (threadIdx.x < (unsigned)n4) {
        float acc[8];
#pragma unroll
        for (int k = 0; k < 8; k++) acc[k] = 0.f;
        for (int j = 0; j < rstep; j++) {
            float* p = sm + (c4 + j * n4) * 8;
#pragma unroll
            for (int k = 0; k < 8; k++) acc[k] += p[k];
        }
#pragma unroll
        for (int k = 0; k < 4; k++) {
            atomicAdd(st + c4 * 4 + k, acc[k]);
            atomicAdd(st + ncol + c4 * 4 + k, acc[4 + k]);
        }
    }
}

// ---------------- finalize BN(X): stats -> per-channel scale/shift ----------------
__global__ void finalize_bnX_k(const float* __restrict__ gw, const float* __restrict__ gb) {
    int c = threadIdx.x;  // 128
    float mean = d_stX[c] * (1.f / NN);
    float var = d_stX[CDIM + c] * (1.f / NN) - mean * mean;
    float sc = gw[c] * rsqrtf(var + EPSB);
    d_scX[c] = sc;
    d_shX[c] = gb[c] - mean * sc;
}

// ---------------- fold BN(X) into lin weights/bias; tf32-round all of lin_w ----------------
__global__ void lin_transform_k(const float* __restrict__ lin_w, const float* __restrict__ lin_b) {
    __shared__ float red[128];
    int o = blockIdx.x;   // 0..383
    int t = threadIdx.x;  // 0..127
    const float* wrow = lin_w + (size_t)o * M3;
    float w0 = wrow[t];
    d_linwt[(size_t)o * M3 + t] = rnd_tf32(w0 * d_scX[t]);
    d_linwt[(size_t)o * M3 + 128 + t] = rnd_tf32(wrow[128 + t]);
    d_linwt[(size_t)o * M3 + 256 + t] = rnd_tf32(wrow[256 + t]);
    red[t] = d_shX[t] * w0;
    __syncthreads();
    for (int s2 = 64; s2 > 0; s2 >>= 1) {
        if (t < s2) red[t] += red[t + s2];
        __syncthreads();
    }
    if (t == 0) d_linbt[o] = lin_b[o] + red[0];
}

// ---------------- bnh BN scale/shift from per-graph sums ----------------
__global__ void stats_pool_k(const float* __restrict__ gw, const float* __restrict__ gb) {
    int c = blockIdx.x * 128 + threadIdx.x;  // 0..383
    float ts = 0.f, tq = 0.f;
    for (int g2 = 0; g2 < NG; g2++) {
        ts += d_gsum[g2 * M3 + c];
        tq += d_gsq[g2 * M3 + c];
    }
    float mean = ts * (1.f / NN);
    float var = tq * (1.f / NN) - mean * mean;
    float sc = gw[c] * rsqrtf(var + EPSB);
    d_scH[c] = sc;
    d_shH[c] = gb[c] - mean * sc;
}

// ---------------- emit Hcat (parallel over graphs) ----------------
__global__ void emit_hcat_k() {
    int g2 = blockIdx.x;      // graph
    int c = threadIdx.x;      // 0..383
    float sc = d_scH[c], sh = d_shH[c];
    int cnt = d_gcnt[g2];
    float add = sc * d_gsum[g2 * M3 + c] + sh * (float)cnt;
    float avg = (cnt > 0) ? add / (float)cnt : 0.f;
    float mxv = 0.f;
    if (cnt > 0)
        mxv = (sc >= 0.f) ? fmaf(sc, d_gmax[g2 * M3 + c], sh)
                          : fmaf(sc, d_gmin[g2 * M3 + c], sh);
    d_Hcat[(size_t)g2 * CAT + c] = avg;
    d_Hcat[(size_t)g2 * CAT + 384 + c] = add;
    d_Hcat[(size_t)g2 * CAT + 768 + c] = mxv;
}

// ---------------- BN over graphs ----------------
__global__ void bn_graphs_k(const float* __restrict__ gw, const float* __restrict__ gb) {
    int c = blockIdx.x * blockDim.x + threadIdx.x;
    if (c >= CAT) return;
    float s = 0.f, ss = 0.f;
    for (int r = 0; r < NG; r++) { float v = d_Hcat[r * CAT + c]; s += v; ss += v * v; }
    float mean = s * (1.f / NG);
    float var = ss * (1.f / NG) - mean * mean;
    float sc = gw[c] * rsqrtf(var + EPSB);
    float sh = gb[c] - mean * sc;
    for (int r = 0; r < NG; r++) d_Hbn[r * CAT + c] = fmaf(d_Hcat[r * CAT + c], sc, sh);
}

// ---------------- small dense layer ----------------
__global__ void mlp_k(const float* __restrict__ A, int Kd,
                      const float* __restrict__ W, const float* __restrict__ bias,
                      float* __restrict__ out, int Od, int do_relu) {
    extern __shared__ float sA[];
    int g0 = blockIdx.y * 8;
    for (int idx = threadIdx.x; idx < 8 * Kd; idx += blockDim.x)
        sA[idx] = A[(size_t)(g0 + idx / Kd) * Kd + (idx % Kd)];
    __syncthreads();
    int o = blockIdx.x * blockDim.x + threadIdx.x;
    float bb = bias[o];
    float acc[8];
#pragma unroll
    for (int j = 0; j < 8; j++) acc[j] = bb;
    const float* wr = W + (size_t)o * Kd;
    for (int k = 0; k < Kd; k++) {
        float w = wr[k];
#pragma unroll
        for (int j = 0; j < 8; j++) acc[j] = fmaf(w, sA[j * Kd + k], acc[j]);
    }
#pragma unroll
    for (int j = 0; j < 8; j++) {
        float v = acc[j];
        if (do_relu) v = fmaxf(v, 0.f);
        out[(size_t)(g0 + j) * Od + o] = v;
    }
}

// ---------------- final layer + log_softmax ----------------
__global__ void final_k(const float* __restrict__ w3, const float* __restrict__ b3,
                        float* __restrict__ out) {
    int g = threadIdx.x;
    if (g >= NG) return;
    float l0 = b3[0], l1 = b3[1];
    const float* h = d_h2 + (size_t)g * 384;
    for (int k = 0; k < 384; k++) {
        float v = h[k];
        l0 = fmaf(v, w3[k], l0);
        l1 = fmaf(v, w3[384 + k], l1);
    }
    float m = fmaxf(l0, l1);
    float lse = m + logf(expf(l0 - m) + expf(l1 - m));
    out[g * 2 + 0] = l0 - lse;
    out[g * 2 + 1] = l1 - lse;
}

extern "C" void kernel_launch(void* const* d_in, const int* in_sizes, int n_in,
                              void* d_out, int out_size) {
    const float* x      = (const float*)d_in[0];
    const int*   ei     = (const int*)d_in[1];
    const int*   batch  = (const int*)d_in[2];
    const float* w_rel  = (const float*)d_in[4];
    const float* b_rel  = (const float*)d_in[5];
    const float* w_root = (const float*)d_in[6];
    const float* n0g    = (const float*)d_in[7];
    const float* n0b    = (const float*)d_in[8];
    const float* lin_w  = (const float*)d_in[9];
    const float* lin_b  = (const float*)d_in[10];
    const float* bnh_g  = (const float*)d_in[11];
    const float* bnh_b  = (const float*)d_in[12];
    const float* bno_g  = (const float*)d_in[13];
    const float* bno_b  = (const float*)d_in[14];
    const float* w1     = (const float*)d_in[15];
    const float* b1     = (const float*)d_in[16];
    const float* w2     = (const float*)d_in[17];
    const float* b2     = (const float*)d_in[18];
    const float* w3     = (const float*)d_in[19];
    const float* b3     = (const float*)d_in[20];
    float* out = (float*)d_out;
    const int* row = ei;
    const int* col = ei + NE;

    float *p_neigh, *p_Xr, *p_H1, *p_H2, *p_stX, *p_scX, *p_shX;
    float *p_Hbn, *p_h1, *p_h2, *p_xr;
    int *p_offc, *p_offr, *p_srcc, *p_srcr;
    cudaGetSymbolAddress((void**)&p_neigh, d_neigh);
    cudaGetSymbolAddress((void**)&p_Xr, d_Xr);
    cudaGetSymbolAddress((void**)&p_H1, d_H1);
    cudaGetSymbolAddress((void**)&p_H2, d_H2);
    cudaGetSymbolAddress((void**)&p_stX, d_stX);
    cudaGetSymbolAddress((void**)&p_scX, d_scX);
    cudaGetSymbolAddress((void**)&p_shX, d_shX);
    cudaGetSymbolAddress((void**)&p_Hbn, d_Hbn);
    cudaGetSymbolAddress((void**)&p_h1, d_h1);
    cudaGetSymbolAddress((void**)&p_h2, d_h2);
    cudaGetSymbolAddress((void**)&p_xr, d_xr);
    cudaGetSymbolAddress((void**)&p_offc, d_offc);
    cudaGetSymbolAddress((void**)&p_offr, d_offr);
    cudaGetSymbolAddress((void**)&p_srcc, d_srcc);
    cudaGetSymbolAddress((void**)&p_srcr, d_srcr);

    cudaFuncSetAttribute(gemm_x_k, cudaFuncAttributeMaxDynamicSharedMemorySize, GSMEM);
    cudaFuncSetAttribute(gemm_hm_k, cudaFuncAttributeMaxDynamicSharedMemorySize, GSMEM);

    const int ROWBLK = (NN + 127) / 128;   // 391
    const int NODEBLK = (NN + 7) / 8;      // 6250

    // ---- CSR build + operand rounding ----
    init_k<<<(NN + 255) / 256, 256>>>();
    hist_k<<<(NE + 255) / 256, 256>>>(row, col);
    scan_k<<<2, SCAN_T>>>();
    fill_k<<<(NE + 255) / 256, 256>>>(row, col);
    gcnt_k<<<1, NG>>>(batch);
    round_copy_k<<<(NN * CDIM + 255) / 256, 256>>>(x, p_xr, NN * CDIM);
    round_weights_k<<<(CDIM * CDIM) / 256, 256>>>(w_rel, w_root);
    // neigh[n] = sum (dst=col) of x[src]  (stored tf32-rounded)
    spmm_csr_k<<<NODEBLK, 256>>>(x, p_neigh, p_offc, p_srcc, nullptr, nullptr);
    // Xr = tf32( neigh @ w_rel^T + x @ w_root^T + b_rel )
    gemm_x_k<<<ROWBLK, 256, GSMEM>>>(b_rel);
    stats2_k<<<400, 256>>>(p_Xr, 128, p_stX, 125);
    finalize_bnX_k<<<1, 128>>>(n0g, n0b);
    lin_transform_k<<<M3, 128>>>(lin_w, lin_b);
    // H1 = A·BN(Xr) (affine fused, rounded); H2 = A·H1 (rounded)
    spmm_csr_k<<<NODEBLK, 256>>>(p_Xr, p_H1, p_offr, p_srcr, p_scX, p_shX);
    spmm_csr_k<<<NODEBLK, 256>>>(p_H1, p_H2, p_offr, p_srcr, nullptr, nullptr);
    // masked block-lower-triangular lin GEMM with pooling fused into epilogue
    gemm_hm_k<<<dim3(ROWBLK, 3), 256, GSMEM>>>(batch);
    // bnh BN stats from per-graph sums; emit pooled features
    stats_pool_k<<<3, 128>>>(bnh_g, bnh_b);
    emit_hcat_k<<<NG, 384>>>();
    bn_graphs_k<<<CAT / 128, 128>>>(bno_g, bno_b);
    mlp_k<<<dim3(768 / 128, NG / 8), 128, 8 * 1152 * sizeof(float)>>>(
        p_Hbn, 1152, w1, b1, p_h1, 768, 1);
    mlp_k<<<dim3(384 / 128, NG / 8), 128, 8 * 768 * sizeof(float)>>>(
        p_h1, 768, w2, b2, p_h2, 384, 1);
    final_k<<<1, 128>>>(w3, b3, out);
}

// round 17
// speedup vs baseline: 1.0648x; 1.0274x over previous
#include <cuda_runtime.h>
#include <math.h>
#include <stdint.h>

#define NN 50000
#define NE 600000
#define NG 128
#define CDIM 128
#define M3 384
#define CAT 1152
#define EPSB 1e-5f
#define SCAN_T 1024
#define AST 36                       // smem row stride (words)
#define GSMEM (4 * 128 * AST * 4)    // 2 stages x (A+W) x 128x36 words = 73728 B

// ---------------- static scratch (no allocations allowed) ----------------
__device__ float d_neigh[(size_t)NN * CDIM];
__device__ float d_Xr[(size_t)NN * CDIM];
__device__ float d_xr[(size_t)NN * CDIM];
__device__ float d_H1[(size_t)NN * CDIM];
__device__ float d_H2[(size_t)NN * CDIM];
__device__ float d_wrelt[CDIM * CDIM];
__device__ float d_wroott[CDIM * CDIM];
__device__ float d_linwt[M3 * M3];
__device__ float d_linbt[M3];
__device__ float d_stX[2 * CDIM];
__device__ float d_scX[CDIM];
__device__ float d_shX[CDIM];
__device__ float d_scH[M3];
__device__ float d_shH[M3];
__device__ float d_scB[CAT];
__device__ float d_shB[CAT];
__device__ float d_gsum[NG * M3];
__device__ float d_gsq[NG * M3];
__device__ float d_gmax[NG * M3];
__device__ float d_gmin[NG * M3];
__device__ int   d_gcnt[NG];
__device__ float d_Hcat[NG * CAT];
__device__ float d_h1[NG * 768];
__device__ float d_h2[NG * 384];
// CSR scratch
__device__ int d_degc[NN], d_degr[NN];
__device__ int d_offc[NN + 1], d_offr[NN + 1];
__device__ int d_curc[NN], d_curr[NN];
__device__ int d_srcc[NE];
__device__ int d_srcr[NE];

// ---------------- tf32 helpers ----------------
__device__ __forceinline__ unsigned f2tf32(float v) {
    unsigned r;
    asm("cvt.rna.tf32.f32 %0, %1;" : "=r"(r) : "f"(v));
    return r;
}
__device__ __forceinline__ float rnd_tf32(float v) { return __uint_as_float(f2tf32(v)); }
__device__ __forceinline__ void mma_tf32(float* c, const unsigned* a, const unsigned* b) {
    asm volatile(
        "mma.sync.aligned.m16n8k8.row.col.f32.tf32.tf32.f32 "
        "{%0,%1,%2,%3}, {%4,%5,%6,%7}, {%8,%9}, {%0,%1,%2,%3};"
        : "+f"(c[0]), "+f"(c[1]), "+f"(c[2]), "+f"(c[3])
        : "r"(a[0]), "r"(a[1]), "r"(a[2]), "r"(a[3]), "r"(b[0]), "r"(b[1]));
}
// ---------------- float atomic max/min (sign-split trick) ----------------
__device__ __forceinline__ void atomicMaxF(float* a, float v) {
    if (v >= 0.f) atomicMax((int*)a, __float_as_int(v));
    else atomicMin((unsigned*)a, __float_as_uint(v));
}
__device__ __forceinline__ void atomicMinF(float* a, float v) {
    if (v >= 0.f) atomicMin((int*)a, __float_as_int(v));
    else atomicMax((unsigned*)a, __float_as_uint(v));
}
// ---------------- cp.async helpers ----------------
__device__ __forceinline__ void cpa16(uint32_t saddr, const void* g, int bytes) {
    asm volatile("cp.async.cg.shared.global [%0], [%1], 16, %2;"
                 :: "r"(saddr), "l"(g), "r"(bytes));
}
__device__ __forceinline__ void cpa_commit() { asm volatile("cp.async.commit_group;"); }
__device__ __forceinline__ void cpa_wait1() { asm volatile("cp.async.wait_group 1;"); }
__device__ __forceinline__ void cpa_wait0() { asm volatile("cp.async.wait_group 0;"); }

// ---------------- merged prep: init + gcnt + tf32-rounding of x and weights ----------------
__global__ void prep_k(const float* __restrict__ x, const float* __restrict__ wrel,
                       const float* __restrict__ wroot, const int* __restrict__ batch) {
    int i = blockIdx.x * blockDim.x + threadIdx.x;
    if (i < NN * CDIM) d_xr[i] = rnd_tf32(__ldg(x + i));
    if (i < NN) { d_degc[i] = 0; d_degr[i] = 0; }
    if (i < 2 * CDIM) d_stX[i] = 0.f;
    if (i < NG * M3) {
        d_gsum[i] = 0.f;
        d_gsq[i] = 0.f;
        d_gmax[i] = -INFINITY;
        d_gmin[i] = INFINITY;
    }
    if (i < CDIM * CDIM) {
        d_wrelt[i] = rnd_tf32(__ldg(wrel + i));
        d_wroott[i] = rnd_tf32(__ldg(wroot + i));
    }
    if (i < NG) {
        int g = i;
        int lo = 0, hi = NN;
        while (lo < hi) { int m = (lo + hi) >> 1; if (batch[m] < g) lo = m + 1; else hi = m; }
        int start = lo;
        lo = start; hi = NN;
        while (lo < hi) { int m = (lo + hi) >> 1; if (batch[m] < g + 1) lo = m + 1; else hi = m; }
        d_gcnt[g] = lo - start;
    }
}

// ---------------- degree histogram ----------------
__global__ void hist_k(const int* __restrict__ row, const int* __restrict__ col) {
    int e = blockIdx.x * blockDim.x + threadIdx.x;
    if (e >= NE) return;
    atomicAdd(&d_degc[__ldg(col + e)], 1);
    atomicAdd(&d_degr[__ldg(row + e)], 1);
}

// ---------------- exclusive scan (single block per array) ----------------
__global__ void scan_k() {
    __shared__ int sm[SCAN_T];
    const int* deg = (blockIdx.x == 0) ? d_degc : d_degr;
    int* off = (blockIdx.x == 0) ? d_offc : d_offr;
    int* cur = (blockIdx.x == 0) ? d_curc : d_curr;
    int t = threadIdx.x;
    const int CH = (NN + SCAN_T - 1) / SCAN_T;
    int b = t * CH, e = min(b + CH, NN);
    int s = 0;
    for (int i = b; i < e; i++) s += deg[i];
    sm[t] = s;
    __syncthreads();
    for (int d = 1; d < SCAN_T; d <<= 1) {
        int u = (t >= d) ? sm[t - d] : 0;
        __syncthreads();
        sm[t] += u;
        __syncthreads();
    }
    int p = (t == 0) ? 0 : sm[t - 1];
    for (int i = b; i < e; i++) {
        off[i] = p;
        cur[i] = p;
        p += deg[i];
    }
    if (t == SCAN_T - 1) off[NN] = sm[SCAN_T - 1];
}

// ---------------- fill CSR edge lists ----------------
__global__ void fill_k(const int* __restrict__ row, const int* __restrict__ col) {
    int e = blockIdx.x * blockDim.x + threadIdx.x;
    if (e >= NE) return;
    int r = __ldg(row + e), c = __ldg(col + e);
    int pc = atomicAdd(&d_curc[c], 1);
    d_srcc[pc] = r;
    int pr = atomicAdd(&d_curr[r], 1);
    d_srcr[pr] = c;
}

// ---------------- CSR gather-accumulate (MLP-4 unrolled); stores tf32-rounded ----------------
__global__ void spmm_csr_k(const float* __restrict__ src, float* __restrict__ dst,
                           const int* __restrict__ off, const int* __restrict__ idx,
                           const float* __restrict__ sc, const float* __restrict__ sh) {
    int node = blockIdx.x * 8 + (threadIdx.x >> 5);
    if (node >= NN) return;
    int q = threadIdx.x & 31;
    int beg = __ldg(off + node), end = __ldg(off + node + 1);
    float4 acc = make_float4(0.f, 0.f, 0.f, 0.f);
    int e = beg;
    for (; e + 3 < end; e += 4) {
        int s0 = __ldg(idx + e), s1 = __ldg(idx + e + 1);
        int s2 = __ldg(idx + e + 2), s3 = __ldg(idx + e + 3);
        float4 v0 = __ldg((const float4*)src + (size_t)s0 * 32 + q);
        float4 v1 = __ldg((const float4*)src + (size_t)s1 * 32 + q);
        float4 v2 = __ldg((const float4*)src + (size_t)s2 * 32 + q);
        float4 v3 = __ldg((const float4*)src + (size_t)s3 * 32 + q);
        acc.x += (v0.x + v1.x) + (v2.x + v3.x);
        acc.y += (v0.y + v1.y) + (v2.y + v3.y);
        acc.z += (v0.z + v1.z) + (v2.z + v3.z);
        acc.w += (v0.w + v1.w) + (v2.w + v3.w);
    }
    for (; e < end; ++e) {
        int s0 = __ldg(idx + e);
        float4 v0 = __ldg((const float4*)src + (size_t)s0 * 32 + q);
        acc.x += v0.x; acc.y += v0.y; acc.z += v0.z; acc.w += v0.w;
    }
    if (sc) {
        float d = (float)(end - beg);
        float4 s4 = __ldg((const float4*)sc + q);
        float4 h4 = __ldg((const float4*)sh + q);
        acc.x = fmaf(acc.x, s4.x, h4.x * d);
        acc.y = fmaf(acc.y, s4.y, h4.y * d);
        acc.z = fmaf(acc.z, s4.z, h4.z * d);
        acc.w = fmaf(acc.w, s4.w, h4.w * d);
    }
    acc.x = rnd_tf32(acc.x); acc.y = rnd_tf32(acc.y);
    acc.z = rnd_tf32(acc.z); acc.w = rnd_tf32(acc.w);
    ((float4*)dst)[(size_t)node * 32 + q] = acc;
}

// ---------------- stage issue helper for async GEMM ----------------
__device__ __forceinline__ void gemm_issue_stage(
    const float* const* Ap, const float* const* Wp, int st, int ldw,
    int r0, int rrb, int kq, uint32_t sbase, int BUF) {
    const float* A = Ap[st >> 2];
    const float* W = Wp[st >> 2];
    int kb = (st & 3) * 32;
    uint32_t abase = sbase + (uint32_t)((st & 1) * BUF) * 4;
    uint32_t wbase = abase + 128 * AST * 4;
#pragma unroll
    for (int it = 0; it < 4; ++it) {
        int rr = rrb + it * 32;
        int r = r0 + rr;
        int ok = (r < NN);
        const float* ga = A + (size_t)(ok ? r : 0) * CDIM + kb + kq;
        cpa16(abase + (uint32_t)(rr * AST + kq) * 4, ga, ok ? 16 : 0);
        cpa16(wbase + (uint32_t)(rr * AST + kq) * 4, W + (size_t)rr * ldw + kb + kq, 16);
    }
    cpa_commit();
}

// ================= tf32 GEMM core, cp.async double-buffered =================
// pool_batch == nullptr : normal epilogue writing Cp (optionally tf32-rounded)
// pool_batch != nullptr : pooling epilogue — per-graph sum/sumsq/max/min atomics
__device__ __forceinline__ void gemm_core_async(
    const float* const* Ap, const float* const* Wp, int nIn, int ldw,
    const float* __restrict__ bias, float* __restrict__ Cp, int ldc,
    int r0, int cbase, int round_primary, const int* __restrict__ pool_batch,
    unsigned* smemu) {
    const int tx = threadIdx.x;
    const int lane = tx & 31;
    const int warp = tx >> 5;
    const int wr = (warp & 3) * 32;
    const int wc = (warp >> 2) * 64;
    const int g = lane >> 2;
    const int t4 = lane & 3;
    const int rrb = tx >> 3;        // 0..31
    const int kq = (tx & 7) * 4;    // 0..28
    const uint32_t sbase = (uint32_t)__cvta_generic_to_shared(smemu);
    const int BUF = 2 * 128 * AST;  // words per stage (A+W)

    float acc[2][8][4];
#pragma unroll
    for (int mi = 0; mi < 2; mi++)
#pragma unroll
        for (int ni = 0; ni < 8; ni++)
#pragma unroll
            for (int j = 0; j < 4; j++) acc[mi][ni][j] = 0.f;

    const int nSteps = nIn * 4;

    gemm_issue_stage(Ap, Wp, 0, ldw, r0, rrb, kq, sbase, BUF);
    for (int st = 0; st < nSteps; ++st) {
        if (st + 1 < nSteps) {
            gemm_issue_stage(Ap, Wp, st + 1, ldw, r0, rrb, kq, sbase, BUF);
            cpa_wait1();
        } else {
            cpa_wait0();
        }
        __syncthreads();
        const unsigned* Ab = smemu + (st & 1) * BUF;
        const unsigned* Wb = Ab + 128 * AST;
#pragma unroll
        for (int kk = 0; kk < 32; kk += 8) {
            unsigned a[2][4], b[8][2];
#pragma unroll
            for (int mi = 0; mi < 2; mi++) {
                int r = wr + mi * 16;
                a[mi][0] = Ab[(r + g) * AST + kk + t4];
                a[mi][1] = Ab[(r + g + 8) * AST + kk + t4];
                a[mi][2] = Ab[(r + g) * AST + kk + t4 + 4];
                a[mi][3] = Ab[(r + g + 8) * AST + kk + t4 + 4];
            }
#pragma unroll
            for (int ni = 0; ni < 8; ni++) {
                int n = wc + ni * 8 + g;
                b[ni][0] = Wb[n * AST + kk + t4];
                b[ni][1] = Wb[n * AST + kk + t4 + 4];
            }
#pragma unroll
            for (int mi = 0; mi < 2; mi++)
#pragma unroll
                for (int ni = 0; ni < 8; ni++)
                    mma_tf32(acc[mi][ni], a[mi], b[ni]);
        }
        __syncthreads();
    }

    if (!pool_batch) {
#pragma unroll
        for (int mi = 0; mi < 2; mi++) {
            int r1 = r0 + wr + mi * 16 + g;
            int r2 = r1 + 8;
#pragma unroll
            for (int ni = 0; ni < 8; ni++) {
                int cc = wc + ni * 8 + 2 * t4;
                float b0 = bias[cc], b1 = bias[cc + 1];
                if (r1 < NN) {
                    float v0 = acc[mi][ni][0] + b0, v1 = acc[mi][ni][1] + b1;
                    if (round_primary) { v0 = rnd_tf32(v0); v1 = rnd_tf32(v1); }
                    Cp[(size_t)r1 * ldc + cbase + cc] = v0;
                    Cp[(size_t)r1 * ldc + cbase + cc + 1] = v1;
                }
                if (r2 < NN) {
                    float v2 = acc[mi][ni][2] + b0, v3 = acc[mi][ni][3] + b1;
                    if (round_primary) { v2 = rnd_tf32(v2); v3 = rnd_tf32(v3); }
                    Cp[(size_t)r2 * ldc + cbase + cc] = v2;
                    Cp[(size_t)r2 * ldc + cbase + cc + 1] = v3;
                }
            }
        }
        return;
    }

    // pooling epilogue: stage tile in smem (stride 129), segment-reduce per column
    float* sv = (float*)smemu;              // 128 x 129 floats
    int* sbatch = (int*)(smemu + 16512);    // 128 ints
#pragma unroll
    for (int mi = 0; mi < 2; mi++) {
        int lr1 = wr + mi * 16 + g;
        int lr2 = lr1 + 8;
#pragma unroll
        for (int ni = 0; ni < 8; ni++) {
            int cc = wc + ni * 8 + 2 * t4;
            float b0 = bias[cc], b1 = bias[cc + 1];
            sv[lr1 * 129 + cc] = acc[mi][ni][0] + b0;
            sv[lr1 * 129 + cc + 1] = acc[mi][ni][1] + b1;
            sv[lr2 * 129 + cc] = acc[mi][ni][2] + b0;
            sv[lr2 * 129 + cc + 1] = acc[mi][ni][3] + b1;
        }
    }
    if (tx < 128) sbatch[tx] = (r0 + tx < NN) ? __ldg(pool_batch + r0 + tx) : -1;
    __syncthreads();
    if (tx < 128) {
        int c = tx;
        float s = 0.f, q = 0.f, mx = 0.f, mn = 0.f;
        int cur = -1;
        for (int r = 0; r < 128; ++r) {
            int bg = sbatch[r];
            if (bg < 0) break;
            float v = sv[r * 129 + c];
            if (bg != cur) {
                if (cur >= 0) {
                    atomicAdd(&d_gsum[cur * M3 + cbase + c], s);
                    atomicAdd(&d_gsq[cur * M3 + cbase + c], q);
                    atomicMaxF(&d_gmax[cur * M3 + cbase + c], mx);
                    atomicMinF(&d_gmin[cur * M3 + cbase + c], mn);
                }
                cur = bg; s = v; q = v * v; mx = v; mn = v;
            } else {
                s += v; q += v * v;
                mx = fmaxf(mx, v); mn = fminf(mn, v);
            }
        }
        if (cur >= 0) {
            atomicAdd(&d_gsum[cur * M3 + cbase + c], s);
            atomicAdd(&d_gsq[cur * M3 + cbase + c], q);
            atomicMaxF(&d_gmax[cur * M3 + cbase + c], mx);
            atomicMinF(&d_gmin[cur * M3 + cbase + c], mn);
        }
    }
}

// Xr = tf32( neigh @ w_rel^T + xr @ w_root^T + b_rel )
__global__ void __launch_bounds__(256, 2) gemm_x_k(const float* __restrict__ bias) {
    extern __shared__ unsigned smemu[];
    const float* Ap[3] = {d_neigh, d_xr, nullptr};
    const float* Wp[3] = {d_wrelt, d_wroott, nullptr};
    gemm_core_async(Ap, Wp, 2, 128, bias, d_Xr, 128, blockIdx.x * 128, 0, 1,
                    nullptr, smemu);
}

// Hm strips, BN folded into weights; pooling fused into epilogue (no Hm tensor)
__global__ void __launch_bounds__(256, 2) gemm_hm_k(const int* __restrict__ batch) {
    extern __shared__ unsigned smemu[];
    int j = blockIdx.y;
    const float* Ap[3] = {d_Xr, d_H1, d_H2};
    const float* Wp[3];
    for (int i = 0; i < 3; i++)
        Wp[i] = d_linwt + (size_t)(j * 128) * M3 + i * 128;
    gemm_core_async(Ap, Wp, j + 1, M3, d_linbt + j * 128, nullptr, M3,
                    blockIdx.x * 128, j * 128, 0, batch, smemu);
}

// ---------------- per-column sum/sumsq over NN rows (X only) ----------------
__global__ void stats2_k(const float* __restrict__ A, int ncol, float* __restrict__ st,
                         int rows_per_blk) {
    __shared__ float sm[384 * 8];
    int n4 = ncol >> 2;
    int c4 = threadIdx.x % n4;
    int rl = threadIdx.x / n4;
    int rstep = blockDim.x / n4;
    int r0 = blockIdx.x * rows_per_blk;
    int rend = min(r0 + rows_per_blk, NN);
    float4 s = make_float4(0, 0, 0, 0), q = make_float4(0, 0, 0, 0);
    for (int r = r0 + rl; r < rend; r += rstep) {
        float4 v = __ldg((const float4*)(A + (size_t)r * ncol) + c4);
        s.x += v.x; s.y += v.y; s.z += v.z; s.w += v.w;
        q.x += v.x * v.x; q.y += v.y * v.y; q.z += v.z * v.z; q.w += v.w * v.w;
    }
    float* my = sm + threadIdx.x * 8;
    my[0] = s.x; my[1] = s.y; my[2] = s.z; my[3] = s.w;
    my[4] = q.x; my[5] = q.y; my[6] = q.z; my[7] = q.w;
    __syncthreads();
    if (threadIdx.x < (unsigned)n4) {
        float acc[8];
#pragma unroll
        for (int k = 0; k < 8; k++) acc[k] = 0.f;
        for (int j = 0; j < rstep; j++) {
            float* p = sm + (c4 + j * n4) * 8;
#pragma unroll
            for (int k = 0; k < 8; k++) acc[k] += p[k];
        }
#pragma unroll
        for (int k = 0; k < 4; k++) {
            atomicAdd(st + c4 * 4 + k, acc[k]);
            atomicAdd(st + ncol + c4 * 4 + k, acc[4 + k]);
        }
    }
}

// ---------------- finalize BN(X): stats -> per-channel scale/shift ----------------
__global__ void finalize_bnX_k(const float* __restrict__ gw, const float* __restrict__ gb) {
    int c = threadIdx.x;  // 128
    float mean = d_stX[c] * (1.f / NN);
    float var = d_stX[CDIM + c] * (1.f / NN) - mean * mean;
    float sc = gw[c] * rsqrtf(var + EPSB);
    d_scX[c] = sc;
    d_shX[c] = gb[c] - mean * sc;
}

// ---------------- fold BN(X) into lin weights/bias; tf32-round all of lin_w ----------------
__global__ void lin_transform_k(const float* __restrict__ lin_w, const float* __restrict__ lin_b) {
    __shared__ float red[128];
    int o = blockIdx.x;   // 0..383
    int t = threadIdx.x;  // 0..127
    const float* wrow = lin_w + (size_t)o * M3;
    float w0 = wrow[t];
    d_linwt[(size_t)o * M3 + t] = rnd_tf32(w0 * d_scX[t]);
    d_linwt[(size_t)o * M3 + 128 + t] = rnd_tf32(wrow[128 + t]);
    d_linwt[(size_t)o * M3 + 256 + t] = rnd_tf32(wrow[256 + t]);
    red[t] = d_shX[t] * w0;
    __syncthreads();
    for (int s2 = 64; s2 > 0; s2 >>= 1) {
        if (t < s2) red[t] += red[t + s2];
        __syncthreads();
    }
    if (t == 0) d_linbt[o] = lin_b[o] + red[0];
}

// ---------------- bnh BN scale/shift from per-graph sums ----------------
__global__ void stats_pool_k(const float* __restrict__ gw, const float* __restrict__ gb) {
    int c = blockIdx.x * 128 + threadIdx.x;  // 0..383
    float ts = 0.f, tq = 0.f;
    for (int g2 = 0; g2 < NG; g2++) {
        ts += d_gsum[g2 * M3 + c];
        tq += d_gsq[g2 * M3 + c];
    }
    float mean = ts * (1.f / NN);
    float var = tq * (1.f / NN) - mean * mean;
    float sc = gw[c] * rsqrtf(var + EPSB);
    d_scH[c] = sc;
    d_shH[c] = gb[c] - mean * sc;
}

// ---------------- emit Hcat (parallel over graphs) ----------------
__global__ void emit_hcat_k() {
    int g2 = blockIdx.x;      // graph
    int c = threadIdx.x;      // 0..383
    float sc = d_scH[c], sh = d_shH[c];
    int cnt = d_gcnt[g2];
    float add = sc * d_gsum[g2 * M3 + c] + sh * (float)cnt;
    float avg = (cnt > 0) ? add / (float)cnt : 0.f;
    float mxv = 0.f;
    if (cnt > 0)
        mxv = (sc >= 0.f) ? fmaf(sc, d_gmax[g2 * M3 + c], sh)
                          : fmaf(sc, d_gmin[g2 * M3 + c], sh);
    d_Hcat[(size_t)g2 * CAT + c] = avg;
    d_Hcat[(size_t)g2 * CAT + 384 + c] = add;
    d_Hcat[(size_t)g2 * CAT + 768 + c] = mxv;
}

// ---------------- BN over graphs: stats only -> scB/shB ----------------
__global__ void bn_stats_k(const float* __restrict__ gw, const float* __restrict__ gb) {
    int c = blockIdx.x * blockDim.x + threadIdx.x;
    if (c >= CAT) return;
    float s = 0.f, ss = 0.f;
    for (int r = 0; r < NG; r++) { float v = d_Hcat[r * CAT + c]; s += v; ss += v * v; }
    float mean = s * (1.f / NG);
    float var = ss * (1.f / NG) - mean * mean;
    float sc = gw[c] * rsqrtf(var + EPSB);
    d_scB[c] = sc;
    d_shB[c] = gb[c] - mean * sc;
}

// ---------------- small dense layer (optional per-column affine on input) ----------------
__global__ void mlp_k(const float* __restrict__ A, int Kd,
                      const float* __restrict__ W, const float* __restrict__ bias,
                      float* __restrict__ out, int Od, int do_relu,
                      const float* __restrict__ asc, const float* __restrict__ ash) {
    extern __shared__ float sA[];
    int g0 = blockIdx.y * 8;
    for (int idx = threadIdx.x; idx < 8 * Kd; idx += blockDim.x) {
        int kcol = idx % Kd;
        float v = A[(size_t)(g0 + idx / Kd) * Kd + kcol];
        if (asc) v = fmaf(v, asc[kcol], ash[kcol]);
        sA[idx] = v;
    }
    __syncthreads();
    int o = blockIdx.x * blockDim.x + threadIdx.x;
    float bb = bias[o];
    float acc[8];
#pragma unroll
    for (int j = 0; j < 8; j++) acc[j] = bb;
    const float* wr = W + (size_t)o * Kd;
    for (int k = 0; k < Kd; k++) {
        float w = wr[k];
#pragma unroll
        for (int j = 0; j < 8; j++) acc[j] = fmaf(w, sA[j * Kd + k], acc[j]);
    }
#pragma unroll
    for (int j = 0; j < 8; j++) {
        float v = acc[j];
        if (do_relu) v = fmaxf(v, 0.f);
        out[(size_t)(g0 + j) * Od + o] = v;
    }
}

// ---------------- final layer + log_softmax ----------------
__global__ void final_k(const float* __restrict__ w3, const float* __restrict__ b3,
                        float* __restrict__ out) {
    int g = threadIdx.x;
    if (g >= NG) return;
    float l0 = b3[0], l1 = b3[1];
    const float* h = d_h2 + (size_t)g * 384;
    for (int k = 0; k < 384; k++) {
        float v = h[k];
        l0 = fmaf(v, w3[k], l0);
        l1 = fmaf(v, w3[384 + k], l1);
    }
    float m = fmaxf(l0, l1);
    float lse = m + logf(expf(l0 - m) + expf(l1 - m));
    out[g * 2 + 0] = l0 - lse;
    out[g * 2 + 1] = l1 - lse;
}

extern "C" void kernel_launch(void* const* d_in, const int* in_sizes, int n_in,
                              void* d_out, int out_size) {
    const float* x      = (const float*)d_in[0];
    const int*   ei     = (const int*)d_in[1];
    const int*   batch  = (const int*)d_in[2];
    const float* w_rel  = (const float*)d_in[4];
    const float* b_rel  = (const float*)d_in[5];
    const float* w_root = (const float*)d_in[6];
    const float* n0g    = (const float*)d_in[7];
    const float* n0b    = (const float*)d_in[8];
    const float* lin_w  = (const float*)d_in[9];
    const float* lin_b  = (const float*)d_in[10];
    const float* bnh_g  = (const float*)d_in[11];
    const float* bnh_b  = (const float*)d_in[12];
    const float* bno_g  = (const float*)d_in[13];
    const float* bno_b  = (const float*)d_in[14];
    const float* w1     = (const float*)d_in[15];
    const float* b1     = (const float*)d_in[16];
    const float* w2     = (const float*)d_in[17];
    const float* b2     = (const float*)d_in[18];
    const float* w3     = (const float*)d_in[19];
    const float* b3     = (const float*)d_in[20];
    float* out = (float*)d_out;
    const int* row = ei;
    const int* col = ei + NE;

    float *p_neigh, *p_Xr, *p_H1, *p_H2, *p_stX, *p_scX, *p_shX;
    float *p_Hcat, *p_h1, *p_h2, *p_scB, *p_shB;
    int *p_offc, *p_offr, *p_srcc, *p_srcr;
    cudaGetSymbolAddress((void**)&p_neigh, d_neigh);
    cudaGetSymbolAddress((void**)&p_Xr, d_Xr);
    cudaGetSymbolAddress((void**)&p_H1, d_H1);
    cudaGetSymbolAddress((void**)&p_H2, d_H2);
    cudaGetSymbolAddress((void**)&p_stX, d_stX);
    cudaGetSymbolAddress((void**)&p_scX, d_scX);
    cudaGetSymbolAddress((void**)&p_shX, d_shX);
    cudaGetSymbolAddress((void**)&p_Hcat, d_Hcat);
    cudaGetSymbolAddress((void**)&p_h1, d_h1);
    cudaGetSymbolAddress((void**)&p_h2, d_h2);
    cudaGetSymbolAddress((void**)&p_scB, d_scB);
    cudaGetSymbolAddress((void**)&p_shB, d_shB);
    cudaGetSymbolAddress((void**)&p_offc, d_offc);
    cudaGetSymbolAddress((void**)&p_offr, d_offr);
    cudaGetSymbolAddress((void**)&p_srcc, d_srcc);
    cudaGetSymbolAddress((void**)&p_srcr, d_srcr);

    cudaFuncSetAttribute(gemm_x_k, cudaFuncAttributeMaxDynamicSharedMemorySize, GSMEM);
    cudaFuncSetAttribute(gemm_hm_k, cudaFuncAttributeMaxDynamicSharedMemorySize, GSMEM);

    const int ROWBLK = (NN + 127) / 128;   // 391
    const int NODEBLK = (NN + 7) / 8;      // 6250

    // ---- merged prep (init + gcnt + rounding) + CSR build ----
    prep_k<<<(NN * CDIM + 255) / 256, 256>>>(x, w_rel, w_root, batch);
    hist_k<<<(NE + 255) / 256, 256>>>(row, col);
    scan_k<<<2, SCAN_T>>>();
    fill_k<<<(NE + 255) / 256, 256>>>(row, col);
    // neigh[n] = sum (dst=col) of x[src]  (stored tf32-rounded)
    spmm_csr_k<<<NODEBLK, 256>>>(x, p_neigh, p_offc, p_srcc, nullptr, nullptr);
    // Xr = tf32( neigh @ w_rel^T + x @ w_root^T + b_rel )
    gemm_x_k<<<ROWBLK, 256, GSMEM>>>(b_rel);
    stats2_k<<<400, 256>>>(p_Xr, 128, p_stX, 125);
    finalize_bnX_k<<<1, 128>>>(n0g, n0b);
    lin_transform_k<<<M3, 128>>>(lin_w, lin_b);
    // H1 = A·BN(Xr) (affine fused, rounded); H2 = A·H1 (rounded)
    spmm_csr_k<<<NODEBLK, 256>>>(p_Xr, p_H1, p_offr, p_srcr, p_scX, p_shX);
    spmm_csr_k<<<NODEBLK, 256>>>(p_H1, p_H2, p_offr, p_srcr, nullptr, nullptr);
    // masked block-lower-triangular lin GEMM with pooling fused into epilogue
    gemm_hm_k<<<dim3(ROWBLK, 3), 256, GSMEM>>>(batch);
    // bnh BN stats from per-graph sums; emit pooled features
    stats_pool_k<<<3, 128>>>(bnh_g, bnh_b);
    emit_hcat_k<<<NG, 384>>>();
    // bno BN as stats-only; affine applied inside first MLP's smem load
    bn_stats_k<<<CAT / 128, 128>>>(bno_g, bno_b);
    mlp_k<<<dim3(768 / 128, NG / 8), 128, 8 * 1152 * sizeof(float)>>>(
        p_Hcat, 1152, w1, b1, p_h1, 768, 1, p_scB, p_shB);
    mlp_k<<<dim3(384 / 128, NG / 8), 128, 8 * 768 * sizeof(float)>>>(
        p_h1, 768, w2, b2, p_h2, 384, 1, nullptr, nullptr);
    final_k<<<1, 128>>>(w3, b3, out);
}